// round 12
// baseline (speedup 1.0000x reference)
#include <cuda_runtime.h>
#include <cuda_fp16.h>
#include <cstdint>

#define DIMX   256
#define HEADS  8
#define BATCH  256
#define NQ     256
#define NK     576
#define DH     32
#define SCALE  0.17677669529663687f

// ---------------- scratch (device globals: no allocations allowed) ----------
__device__ __align__(16) __half g_qwh[(size_t)BATCH * NQ * DIMX];
__device__ __align__(16) __half g_kvwh[(size_t)BATCH * NK * DIMX];
__device__ __align__(16) __half g_wqh[DIMX * DIMX];
__device__ __align__(16) __half g_wkvh[DIMX * 2 * DIMX];
__device__ __align__(16) __half g_wph[DIMX * DIMX];
__device__ __align__(16) __half g_qph[(size_t)BATCH * NQ * DIMX];
__device__ __align__(16) __half g_kvph[(size_t)BATCH * NK * 2 * DIMX];
__device__ __align__(16) __half g_biash[(size_t)HEADS * NQ * NK];
__device__ __align__(16) __half g_aoh[(size_t)BATCH * NQ * DIMX];

__device__ __forceinline__ void cp16(uint32_t dst, const void* src) {
    asm volatile("cp.async.cg.shared.global [%0], [%1], 16;\n" :: "r"(dst), "l"(src));
}
__device__ __forceinline__ void cp_commit() {
    asm volatile("cp.async.commit_group;\n");
}
template <int N>
__device__ __forceinline__ void cp_wait() {
    asm volatile("cp.async.wait_group %0;\n" :: "n"(N));
}
__device__ __forceinline__ void ldsm4(uint32_t addr, uint32_t& r0, uint32_t& r1,
                                      uint32_t& r2, uint32_t& r3) {
    asm volatile("ldmatrix.sync.aligned.m8n8.x4.shared.b16 {%0,%1,%2,%3}, [%4];"
                 : "=r"(r0), "=r"(r1), "=r"(r2), "=r"(r3) : "r"(addr));
}
__device__ __forceinline__ void ldsm4t(uint32_t addr, uint32_t& r0, uint32_t& r1,
                                       uint32_t& r2, uint32_t& r3) {
    asm volatile("ldmatrix.sync.aligned.m8n8.x4.trans.shared.b16 {%0,%1,%2,%3}, [%4];"
                 : "=r"(r0), "=r"(r1), "=r"(r2), "=r"(r3) : "r"(addr));
}
__device__ __forceinline__ void mma16816(float* c, uint32_t a0, uint32_t a1, uint32_t a2,
                                         uint32_t a3, uint32_t b0, uint32_t b1) {
    asm volatile(
        "mma.sync.aligned.m16n8k16.row.col.f32.f16.f16.f32 "
        "{%0,%1,%2,%3},{%4,%5,%6,%7},{%8,%9},{%0,%1,%2,%3};"
        : "+f"(c[0]), "+f"(c[1]), "+f"(c[2]), "+f"(c[3])
        : "r"(a0), "r"(a1), "r"(a2), "r"(a3), "r"(b0), "r"(b1));
}
__device__ __forceinline__ uint32_t h2pack(float lo, float hi) {
    __half2 h = __floats2half2_rn(lo, hi);
    return *reinterpret_cast<uint32_t*>(&h);
}

// ---------------- f32 -> f16 conversion (big activations) -------------------
__global__ void f2h(const float4* __restrict__ src, __half* __restrict__ dst, int n4) {
    int i = blockIdx.x * 256 + threadIdx.x;
    if (i >= n4) return;
    float4 v = src[i];
    __half2* d = (__half2*)dst;
    d[i * 2 + 0] = __floats2half2_rn(v.x, v.y);
    d[i * 2 + 1] = __floats2half2_rn(v.z, v.w);
}

// ---------------- fused conversion of the three weight matrices -------------
// jobs laid out linearly in float4 units: q_W [0,16384) | kv_W [16384,49152) |
// proj_W [49152,65536)
__global__ void prep_weights(const float4* __restrict__ qW,
                             const float4* __restrict__ kvW,
                             const float4* __restrict__ pW,
                             __half* __restrict__ wq,
                             __half* __restrict__ wkv,
                             __half* __restrict__ wp) {
    int i = blockIdx.x * 256 + threadIdx.x;   // < 65536
    const float4* src;
    __half2* dst;
    int off;
    if (i < 16384) { src = qW; dst = (__half2*)wq; off = i; }
    else if (i < 49152) { src = kvW; dst = (__half2*)wkv; off = i - 16384; }
    else { src = pW; dst = (__half2*)wp; off = i - 49152; }
    float4 v = src[off];
    dst[off * 2 + 0] = __floats2half2_rn(v.x, v.y);
    dst[off * 2 + 1] = __floats2half2_rn(v.z, v.w);
}

// ---------------- gather relative-position bias -> half [H,Nq,Nk] ----------
__global__ void bias_gather(const float* __restrict__ table,
                            const int* __restrict__ rel,
                            __half* __restrict__ bias_mat) {
    int p = blockIdx.x * 256 + threadIdx.x;
    if (p >= NQ * NK) return;
    int idx = rel[p];
    const float4* t4 = reinterpret_cast<const float4*>(table + (size_t)idx * 8);
    float4 a = t4[0];
    float4 b = t4[1];
    const int PL = NQ * NK;
    bias_mat[0 * PL + p] = __float2half(a.x);
    bias_mat[1 * PL + p] = __float2half(a.y);
    bias_mat[2 * PL + p] = __float2half(a.z);
    bias_mat[3 * PL + p] = __float2half(a.w);
    bias_mat[4 * PL + p] = __float2half(b.x);
    bias_mat[5 * PL + p] = __float2half(b.y);
    bias_mat[6 * PL + p] = __float2half(b.z);
    bias_mat[7 * PL + p] = __float2half(b.w);
}

// ---------------- raw-mma fp16 GEMM (unchanged from R10) --------------------
#define LDA 72
#define LDB 136
#define A_STG (128 * LDA)
#define B_STG (64 * LDB)
template <int OUT_HALF>
__global__ void __launch_bounds__(256, 2) gemm_mma(const __half* __restrict__ A,
                                                   const __half* __restrict__ W,
                                                   const float* __restrict__ bias,
                                                   void* __restrict__ Cv, int N) {
    extern __shared__ char smraw[];
    __half* As = (__half*)smraw;
    __half* Bs = As + 2 * A_STG;

    const int tid = threadIdx.x;
    const int w = tid >> 5, lane = tid & 31;
    const int wm = w >> 2, wn = w & 3;
    const int bm = blockIdx.y, bn = blockIdx.x;

    const __half* Ab = A + (size_t)bm * 128 * 256;
    const __half* Wb = W + bn * 128;
    const uint32_t sA = (uint32_t)__cvta_generic_to_shared(As);
    const uint32_t sB = (uint32_t)__cvta_generic_to_shared(Bs);

    auto pref = [&](int kt, int stg) {
#pragma unroll
        for (int it = 0; it < 4; it++) {
            int i = it * 256 + tid;
            int r = i >> 3, c8 = i & 7;
            cp16(sA + (stg * A_STG + r * LDA + c8 * 8) * 2,
                 Ab + (size_t)r * 256 + kt * 64 + c8 * 8);
        }
#pragma unroll
        for (int it = 0; it < 4; it++) {
            int i = it * 256 + tid;
            int r = i >> 4, c8 = i & 15;
            cp16(sB + (stg * B_STG + r * LDB + c8 * 8) * 2,
                 Wb + (size_t)(kt * 64 + r) * N + c8 * 8);
        }
        cp_commit();
    };

    pref(0, 0);
    pref(1, 1);

    float acc[4][4][4];
#pragma unroll
    for (int mt = 0; mt < 4; mt++)
#pragma unroll
        for (int nj = 0; nj < 4; nj++)
#pragma unroll
            for (int e = 0; e < 4; e++) acc[mt][nj][e] = 0.f;

    const int t = lane >> 3, wi = lane & 7;
    const int arow = (t & 1) * 8 + wi, acol = (t >> 1) * 8;
    const int brow = (t & 1) * 8 + wi, bcol = (t >> 1) * 8;

#pragma unroll
    for (int kt = 0; kt < 4; kt++) {
        if (kt < 3) cp_wait<1>(); else cp_wait<0>();
        __syncthreads();

        const uint32_t sAc = sA + ((kt & 1) * A_STG) * 2;
        const uint32_t sBc = sB + ((kt & 1) * B_STG) * 2;

#pragma unroll
        for (int kk = 0; kk < 4; kk++) {
            uint32_t a[4][4];
#pragma unroll
            for (int mt = 0; mt < 4; mt++)
                ldsm4(sAc + ((wm * 64 + mt * 16 + arow) * LDA + kk * 16 + acol) * 2,
                      a[mt][0], a[mt][1], a[mt][2], a[mt][3]);
#pragma unroll
            for (int ng = 0; ng < 2; ng++) {
                uint32_t b0, b1, b2, b3;
                ldsm4t(sBc + ((kk * 16 + brow) * LDB + wn * 32 + ng * 16 + bcol) * 2,
                       b0, b1, b2, b3);
#pragma unroll
                for (int mt = 0; mt < 4; mt++) {
                    mma16816(acc[mt][ng * 2],     a[mt][0], a[mt][1], a[mt][2], a[mt][3], b0, b1);
                    mma16816(acc[mt][ng * 2 + 1], a[mt][0], a[mt][1], a[mt][2], a[mt][3], b2, b3);
                }
            }
        }
        if (kt < 2) {
            __syncthreads();
            pref(kt + 2, kt & 1);
        }
    }

    const int rr = lane >> 2, cc = (lane & 3) * 2;
#pragma unroll
    for (int nj = 0; nj < 4; nj++) {
        int col = bn * 128 + wn * 32 + nj * 8 + cc;
        float b0 = bias[col], b1 = bias[col + 1];
#pragma unroll
        for (int mt = 0; mt < 4; mt++) {
            int row1 = bm * 128 + wm * 64 + mt * 16 + rr;
            float* c = acc[mt][nj];
            if (OUT_HALF) {
                __half* C = (__half*)Cv;
                *(__half2*)(C + (size_t)row1 * N + col) = __floats2half2_rn(c[0] + b0, c[1] + b1);
                *(__half2*)(C + (size_t)(row1 + 8) * N + col) = __floats2half2_rn(c[2] + b0, c[3] + b1);
            } else {
                float* C = (float*)Cv;
                *(float2*)(C + (size_t)row1 * N + col) = make_float2(c[0] + b0, c[1] + b1);
                *(float2*)(C + (size_t)(row1 + 8) * N + col) = make_float2(c[2] + b0, c[3] + b1);
            }
        }
    }
}

// ---------------- flash attention v3 (exact R10 revert) ----------------------
__global__ void __launch_bounds__(512, 1) attn_kernel(const __half* __restrict__ qp,
                                                      const __half* __restrict__ kvp,
                                                      const __half* __restrict__ bias_mat,
                                                      __half* __restrict__ ao) {
    extern __shared__ char smraw[];
    __half* Ksm = (__half*)smraw;            // 2 x 64 x 40
    __half* Vsm = Ksm + 2 * 2560;            // 2 x 64 x 40
    __half* Ost = Vsm + 2 * 2560;            // 256 x 40

    const int bx = blockIdx.x;
    const int h = bx & 7, b = bx >> 3;
    const int tid = threadIdx.x, w = tid >> 5, lane = tid & 31;
    const int LDKV = 2 * DIMX;
    const int q0 = w * 16;

    const __half* Kb = kvp + ((size_t)b * NK) * LDKV + h * DH;
    const __half* Vb = Kb + DIMX;
    const uint32_t sK = (uint32_t)__cvta_generic_to_shared(Ksm);
    const uint32_t sV = (uint32_t)__cvta_generic_to_shared(Vsm);
    const uint32_t sO = (uint32_t)__cvta_generic_to_shared(Ost);

    auto prefKV = [&](int chunk, int buf) {
        int t = tid & 255;
        int r = t >> 2, c8 = t & 3;
        const __half* src = ((tid < 256) ? Kb : Vb) + (size_t)(chunk * 64 + r) * LDKV + c8 * 8;
        uint32_t dst = ((tid < 256) ? sK : sV) + (buf * 2560 + r * 40 + c8 * 8) * 2;
        cp16(dst, src);
    };
    prefKV(0, 0); cp_commit();

    {
        const __half* qsrc = qp + ((size_t)(b * NQ + q0)) * DIMX + h * DH;
#pragma unroll
        for (int i = lane; i < 64; i += 32) {
            int r = i >> 2, c8 = i & 3;
            *(uint4*)(Ost + (q0 + r) * 40 + c8 * 8) =
                *(const uint4*)(qsrc + (size_t)r * DIMX + c8 * 8);
        }
        __syncwarp();
    }
    uint32_t qa[2][4];
    {
        int t = lane >> 3, wi = lane & 7;
        int qrow = q0 + (t & 1) * 8 + wi;
        int qcolbase = (t >> 1) * 8;
#pragma unroll
        for (int kt = 0; kt < 2; kt++)
            ldsm4(sO + (qrow * 40 + qcolbase + kt * 16) * 2,
                  qa[kt][0], qa[kt][1], qa[kt][2], qa[kt][3]);
    }

    const int r1 = q0 + (lane >> 2);
    const int r2 = r1 + 8;
    float m1 = -1e30f, m2 = -1e30f, s1 = 0.f, s2 = 0.f;
    float o[4][4];
#pragma unroll
    for (int j = 0; j < 4; j++)
#pragma unroll
        for (int e = 0; e < 4; e++) o[j][e] = 0.f;

    const __half* bm = bias_mat + (size_t)h * NQ * NK;
    const __half* b1base = bm + (size_t)r1 * NK + (lane & 3) * 2;
    const __half* b2base = bm + (size_t)r2 * NK + (lane & 3) * 2;

    const int kt_t = lane >> 3, kt_wi = lane & 7;
    const int krow_off = (kt_t >> 1) * 8 + kt_wi;
    const int kcol_off = (kt_t & 1) * 8;
    const int vrow_off = (kt_t & 1) * 8 + kt_wi;
    const int vcol_off = (kt_t >> 1) * 8;

    for (int c = 0; c < 9; c++) {
        cp_wait<0>();
        __syncthreads();
        if (c < 8) { prefKV(c + 1, (c + 1) & 1); cp_commit(); }

        const uint32_t sKc = sK + ((c & 1) * 2560) * 2;
        const uint32_t sVc = sV + ((c & 1) * 2560) * 2;

        float s[8][4];
#pragma unroll
        for (int j = 0; j < 8; j++)
#pragma unroll
            for (int e = 0; e < 4; e++) s[j][e] = 0.f;

#pragma unroll
        for (int g = 0; g < 4; g++) {
#pragma unroll
            for (int kt = 0; kt < 2; kt++) {
                uint32_t b0, b1, b2, b3;
                ldsm4(sKc + ((g * 16 + krow_off) * 40 + kt * 16 + kcol_off) * 2,
                      b0, b1, b2, b3);
                mma16816(s[2 * g],     qa[kt][0], qa[kt][1], qa[kt][2], qa[kt][3], b0, b1);
                mma16816(s[2 * g + 1], qa[kt][0], qa[kt][1], qa[kt][2], qa[kt][3], b2, b3);
            }
        }

        const __half* b1p = b1base + c * 64;
        const __half* b2p = b2base + c * 64;
        float cm1 = -1e30f, cm2 = -1e30f;
#pragma unroll
        for (int j = 0; j < 8; j++) {
            __half2 bb1 = *(const __half2*)(b1p + j * 8);
            __half2 bb2 = *(const __half2*)(b2p + j * 8);
            s[j][0] = fmaf(s[j][0], SCALE, __low2float(bb1));
            s[j][1] = fmaf(s[j][1], SCALE, __high2float(bb1));
            s[j][2] = fmaf(s[j][2], SCALE, __low2float(bb2));
            s[j][3] = fmaf(s[j][3], SCALE, __high2float(bb2));
            cm1 = fmaxf(cm1, fmaxf(s[j][0], s[j][1]));
            cm2 = fmaxf(cm2, fmaxf(s[j][2], s[j][3]));
        }
        cm1 = fmaxf(cm1, __shfl_xor_sync(0xffffffffu, cm1, 1));
        cm1 = fmaxf(cm1, __shfl_xor_sync(0xffffffffu, cm1, 2));
        cm2 = fmaxf(cm2, __shfl_xor_sync(0xffffffffu, cm2, 1));
        cm2 = fmaxf(cm2, __shfl_xor_sync(0xffffffffu, cm2, 2));

        float m1n = fmaxf(m1, cm1), m2n = fmaxf(m2, cm2);
        float a1 = __expf(m1 - m1n), a2 = __expf(m2 - m2n);
        float sum1 = 0.f, sum2 = 0.f;
#pragma unroll
        for (int j = 0; j < 8; j++) {
            s[j][0] = __expf(s[j][0] - m1n);
            s[j][1] = __expf(s[j][1] - m1n);
            s[j][2] = __expf(s[j][2] - m2n);
            s[j][3] = __expf(s[j][3] - m2n);
            sum1 += s[j][0] + s[j][1];
            sum2 += s[j][2] + s[j][3];
        }
        sum1 += __shfl_xor_sync(0xffffffffu, sum1, 1);
        sum1 += __shfl_xor_sync(0xffffffffu, sum1, 2);
        sum2 += __shfl_xor_sync(0xffffffffu, sum2, 1);
        sum2 += __shfl_xor_sync(0xffffffffu, sum2, 2);
        s1 = s1 * a1 + sum1;
        s2 = s2 * a2 + sum2;
        m1 = m1n;
        m2 = m2n;

#pragma unroll
        for (int j = 0; j < 4; j++) {
            o[j][0] *= a1; o[j][1] *= a1;
            o[j][2] *= a2; o[j][3] *= a2;
        }

#pragma unroll
        for (int kt = 0; kt < 4; kt++) {
            uint32_t pa0 = h2pack(s[2 * kt][0], s[2 * kt][1]);
            uint32_t pa1 = h2pack(s[2 * kt][2], s[2 * kt][3]);
            uint32_t pa2 = h2pack(s[2 * kt + 1][0], s[2 * kt + 1][1]);
            uint32_t pa3 = h2pack(s[2 * kt + 1][2], s[2 * kt + 1][3]);
#pragma unroll
            for (int vg = 0; vg < 2; vg++) {
                uint32_t b0, b1, b2, b3;
                ldsm4t(sVc + ((kt * 16 + vrow_off) * 40 + vg * 16 + vcol_off) * 2,
                       b0, b1, b2, b3);
                mma16816(o[vg * 2],     pa0, pa1, pa2, pa3, b0, b1);
                mma16816(o[vg * 2 + 1], pa0, pa1, pa2, pa3, b2, b3);
            }
        }
        __syncthreads();
    }

    float inv1 = 1.f / s1, inv2 = 1.f / s2;
#pragma unroll
    for (int j = 0; j < 4; j++) {
        *(__half2*)(Ost + r1 * 40 + j * 8 + (lane & 3) * 2) =
            __floats2half2_rn(o[j][0] * inv1, o[j][1] * inv1);
        *(__half2*)(Ost + r2 * 40 + j * 8 + (lane & 3) * 2) =
            __floats2half2_rn(o[j][2] * inv2, o[j][3] * inv2);
    }
    __syncthreads();
    {
        int row = tid >> 1, seg = tid & 1;
        uint4* dst = (uint4*)(ao + ((size_t)(b * NQ + row)) * DIMX + h * DH + seg * 16);
        dst[0] = *(uint4*)(Ost + row * 40 + seg * 16);
        dst[1] = *(uint4*)(Ost + row * 40 + seg * 16 + 8);
    }
}

// ---------------- launch ----------------------------------------------------
extern "C" void kernel_launch(void* const* d_in, const int* in_sizes, int n_in,
                              void* d_out, int out_size) {
    const float* q_w = (const float*)d_in[0];
    const float* kv_w = (const float*)d_in[1];
    const float* q_W = (const float*)d_in[2];
    const float* q_b = (const float*)d_in[3];
    const float* kv_W = (const float*)d_in[4];
    const float* kv_b = (const float*)d_in[5];
    const float* proj_W = (const float*)d_in[6];
    const float* proj_b = (const float*)d_in[7];
    const float* bias_table = (const float*)d_in[8];
    const int* rel_index = (const int*)d_in[9];
    float* out = (float*)d_out;

    __half *qwh, *kvwh, *wqh, *wkvh, *wph, *qph, *kvph, *biash, *aoh;
    cudaGetSymbolAddress((void**)&qwh, g_qwh);
    cudaGetSymbolAddress((void**)&kvwh, g_kvwh);
    cudaGetSymbolAddress((void**)&wqh, g_wqh);
    cudaGetSymbolAddress((void**)&wkvh, g_wkvh);
    cudaGetSymbolAddress((void**)&wph, g_wph);
    cudaGetSymbolAddress((void**)&qph, g_qph);
    cudaGetSymbolAddress((void**)&kvph, g_kvph);
    cudaGetSymbolAddress((void**)&biash, g_biash);
    cudaGetSymbolAddress((void**)&aoh, g_aoh);

    const int GEMM_SMEM = (2 * A_STG + 2 * B_STG) * 2;           // 71680 B
    const int ATTN_SMEM = (2 * 2560 + 2 * 2560 + 256 * 40) * 2;  // 40960 B

    cudaFuncSetAttribute(gemm_mma<1>, cudaFuncAttributeMaxDynamicSharedMemorySize, GEMM_SMEM);
    cudaFuncSetAttribute(gemm_mma<0>, cudaFuncAttributeMaxDynamicSharedMemorySize, GEMM_SMEM);

    f2h<<<(4194304 + 255) / 256, 256>>>((const float4*)q_w, qwh, 4194304);
    f2h<<<(9437184 + 255) / 256, 256>>>((const float4*)kv_w, kvwh, 9437184);
    prep_weights<<<256, 256>>>((const float4*)q_W, (const float4*)kv_W,
                               (const float4*)proj_W, wqh, wkvh, wph);
    bias_gather<<<(NQ * NK + 255) / 256, 256>>>(bias_table, rel_index, biash);

    gemm_mma<1><<<dim3(2, 512), 256, GEMM_SMEM>>>(qwh, wqh, q_b, qph, 256);
    gemm_mma<1><<<dim3(4, 1152), 256, GEMM_SMEM>>>(kvwh, wkvh, kv_b, kvph, 512);
    attn_kernel<<<BATCH * HEADS, 512, ATTN_SMEM>>>(qph, kvph, biash, aoh);
    gemm_mma<0><<<dim3(2, 512), 256, GEMM_SMEM>>>(aoh, wph, proj_b, out, 256);
}

// round 13
// speedup vs baseline: 1.4786x; 1.4786x over previous
#include <cuda_runtime.h>
#include <cuda_fp16.h>
#include <cstdint>

#define DIMX   256
#define HEADS  8
#define BATCH  256
#define NQ     256
#define NK     576
#define DH     32
#define SCALE  0.17677669529663687f

// ---------------- scratch (device globals: no allocations allowed) ----------
__device__ __align__(16) __half g_qwh[(size_t)BATCH * NQ * DIMX];
__device__ __align__(16) __half g_kvwh[(size_t)BATCH * NK * DIMX];
__device__ __align__(16) __half g_wqh[DIMX * DIMX];
__device__ __align__(16) __half g_wkvh[DIMX * 2 * DIMX];
__device__ __align__(16) __half g_wph[DIMX * DIMX];
__device__ __align__(16) __half g_qph[(size_t)BATCH * NQ * DIMX];
__device__ __align__(16) __half g_kvph[(size_t)BATCH * NK * 2 * DIMX];
__device__ __align__(16) __half g_biash[(size_t)HEADS * NQ * NK];
__device__ __align__(16) __half g_aoh[(size_t)BATCH * NQ * DIMX];

__device__ __forceinline__ void cp16(uint32_t dst, const void* src) {
    asm volatile("cp.async.cg.shared.global [%0], [%1], 16;\n" :: "r"(dst), "l"(src));
}
__device__ __forceinline__ void cp_commit() {
    asm volatile("cp.async.commit_group;\n");
}
template <int N>
__device__ __forceinline__ void cp_wait() {
    asm volatile("cp.async.wait_group %0;\n" :: "n"(N));
}
__device__ __forceinline__ void ldsm4(uint32_t addr, uint32_t& r0, uint32_t& r1,
                                      uint32_t& r2, uint32_t& r3) {
    asm volatile("ldmatrix.sync.aligned.m8n8.x4.shared.b16 {%0,%1,%2,%3}, [%4];"
                 : "=r"(r0), "=r"(r1), "=r"(r2), "=r"(r3) : "r"(addr));
}
__device__ __forceinline__ void ldsm4t(uint32_t addr, uint32_t& r0, uint32_t& r1,
                                       uint32_t& r2, uint32_t& r3) {
    asm volatile("ldmatrix.sync.aligned.m8n8.x4.trans.shared.b16 {%0,%1,%2,%3}, [%4];"
                 : "=r"(r0), "=r"(r1), "=r"(r2), "=r"(r3) : "r"(addr));
}
__device__ __forceinline__ void mma16816(float* c, uint32_t a0, uint32_t a1, uint32_t a2,
                                         uint32_t a3, uint32_t b0, uint32_t b1) {
    asm volatile(
        "mma.sync.aligned.m16n8k16.row.col.f32.f16.f16.f32 "
        "{%0,%1,%2,%3},{%4,%5,%6,%7},{%8,%9},{%0,%1,%2,%3};"
        : "+f"(c[0]), "+f"(c[1]), "+f"(c[2]), "+f"(c[3])
        : "r"(a0), "r"(a1), "r"(a2), "r"(a3), "r"(b0), "r"(b1));
}
__device__ __forceinline__ uint32_t h2pack(float lo, float hi) {
    __half2 h = __floats2half2_rn(lo, hi);
    return *reinterpret_cast<uint32_t*>(&h);
}

// ---------------- f32 -> f16 conversion ------------------------------------
__global__ void f2h(const float4* __restrict__ src, __half* __restrict__ dst, int n4) {
    int i = blockIdx.x * 256 + threadIdx.x;
    if (i >= n4) return;
    float4 v = src[i];
    __half2* d = (__half2*)dst;
    d[i * 2 + 0] = __floats2half2_rn(v.x, v.y);
    d[i * 2 + 1] = __floats2half2_rn(v.z, v.w);
}

// ---------------- gather relative-position bias -> half [H,Nq,Nk] ----------
__global__ void bias_gather(const float* __restrict__ table,
                            const int* __restrict__ rel,
                            __half* __restrict__ bias_mat) {
    int p = blockIdx.x * 256 + threadIdx.x;
    if (p >= NQ * NK) return;
    int idx = rel[p];
    const float4* t4 = reinterpret_cast<const float4*>(table + (size_t)idx * 8);
    float4 a = t4[0];
    float4 b = t4[1];
    const int PL = NQ * NK;
    bias_mat[0 * PL + p] = __float2half(a.x);
    bias_mat[1 * PL + p] = __float2half(a.y);
    bias_mat[2 * PL + p] = __float2half(a.z);
    bias_mat[3 * PL + p] = __float2half(a.w);
    bias_mat[4 * PL + p] = __float2half(b.x);
    bias_mat[5 * PL + p] = __float2half(b.y);
    bias_mat[6 * PL + p] = __float2half(b.z);
    bias_mat[7 * PL + p] = __float2half(b.w);
}

// ---------------- raw-mma fp16 GEMM: C[M,N] = A[M,256] @ W[256,N] + bias ----
// tile 128x128, BK=64, 2-stage cp.async, 2 CTAs/SM, 8 warps (2x4), warp 64x32
#define LDA 72
#define LDB 136
#define A_STG (128 * LDA)     // 9216 halves
#define B_STG (64 * LDB)      // 8704 halves
template <int OUT_HALF>
__global__ void __launch_bounds__(256, 2) gemm_mma(const __half* __restrict__ A,
                                                   const __half* __restrict__ W,
                                                   const float* __restrict__ bias,
                                                   void* __restrict__ Cv, int N) {
    extern __shared__ char smraw[];
    __half* As = (__half*)smraw;          // 2 x 128 x 72
    __half* Bs = As + 2 * A_STG;          // 2 x 64 x 136

    const int tid = threadIdx.x;
    const int w = tid >> 5, lane = tid & 31;
    const int wm = w >> 2, wn = w & 3;    // 2 x 4 warp grid
    const int bm = blockIdx.y, bn = blockIdx.x;

    const __half* Ab = A + (size_t)bm * 128 * 256;
    const __half* Wb = W + bn * 128;
    const uint32_t sA = (uint32_t)__cvta_generic_to_shared(As);
    const uint32_t sB = (uint32_t)__cvta_generic_to_shared(Bs);

    auto pref = [&](int kt, int stg) {
#pragma unroll
        for (int it = 0; it < 4; it++) {          // A: 1024 chunks of 8 halves
            int i = it * 256 + tid;
            int r = i >> 3, c8 = i & 7;
            cp16(sA + (stg * A_STG + r * LDA + c8 * 8) * 2,
                 Ab + (size_t)r * 256 + kt * 64 + c8 * 8);
        }
#pragma unroll
        for (int it = 0; it < 4; it++) {          // B: 1024 chunks
            int i = it * 256 + tid;
            int r = i >> 4, c8 = i & 15;
            cp16(sB + (stg * B_STG + r * LDB + c8 * 8) * 2,
                 Wb + (size_t)(kt * 64 + r) * N + c8 * 8);
        }
        cp_commit();
    };

    pref(0, 0);
    pref(1, 1);

    float acc[4][4][4];
#pragma unroll
    for (int mt = 0; mt < 4; mt++)
#pragma unroll
        for (int nj = 0; nj < 4; nj++)
#pragma unroll
            for (int e = 0; e < 4; e++) acc[mt][nj][e] = 0.f;

    const int t = lane >> 3, wi = lane & 7;
    const int arow = (t & 1) * 8 + wi, acol = (t >> 1) * 8;
    const int brow = (t & 1) * 8 + wi, bcol = (t >> 1) * 8;

#pragma unroll
    for (int kt = 0; kt < 4; kt++) {
        if (kt < 3) cp_wait<1>(); else cp_wait<0>();
        __syncthreads();

        const uint32_t sAc = sA + ((kt & 1) * A_STG) * 2;
        const uint32_t sBc = sB + ((kt & 1) * B_STG) * 2;

#pragma unroll
        for (int kk = 0; kk < 4; kk++) {
            uint32_t a[4][4];
#pragma unroll
            for (int mt = 0; mt < 4; mt++)
                ldsm4(sAc + ((wm * 64 + mt * 16 + arow) * LDA + kk * 16 + acol) * 2,
                      a[mt][0], a[mt][1], a[mt][2], a[mt][3]);
#pragma unroll
            for (int ng = 0; ng < 2; ng++) {
                uint32_t b0, b1, b2, b3;
                ldsm4t(sBc + ((kk * 16 + brow) * LDB + wn * 32 + ng * 16 + bcol) * 2,
                       b0, b1, b2, b3);
#pragma unroll
                for (int mt = 0; mt < 4; mt++) {
                    mma16816(acc[mt][ng * 2],     a[mt][0], a[mt][1], a[mt][2], a[mt][3], b0, b1);
                    mma16816(acc[mt][ng * 2 + 1], a[mt][0], a[mt][1], a[mt][2], a[mt][3], b2, b3);
                }
            }
        }
        if (kt < 2) {
            __syncthreads();               // everyone done reading stage kt&1
            pref(kt + 2, kt & 1);          // refill it
        }
    }

    // epilogue: direct register -> global, bias fused
    const int rr = lane >> 2, cc = (lane & 3) * 2;
#pragma unroll
    for (int nj = 0; nj < 4; nj++) {
        int col = bn * 128 + wn * 32 + nj * 8 + cc;
        float b0 = bias[col], b1 = bias[col + 1];
#pragma unroll
        for (int mt = 0; mt < 4; mt++) {
            int row1 = bm * 128 + wm * 64 + mt * 16 + rr;
            float* c = acc[mt][nj];
            if (OUT_HALF) {
                __half* C = (__half*)Cv;
                *(__half2*)(C + (size_t)row1 * N + col) = __floats2half2_rn(c[0] + b0, c[1] + b1);
                *(__half2*)(C + (size_t)(row1 + 8) * N + col) = __floats2half2_rn(c[2] + b0, c[3] + b1);
            } else {
                float* C = (float*)Cv;
                *(float2*)(C + (size_t)row1 * N + col) = make_float2(c[0] + b0, c[1] + b1);
                *(float2*)(C + (size_t)(row1 + 8) * N + col) = make_float2(c[2] + b0, c[3] + b1);
            }
        }
    }
}

// ---------------- flash attention v3 -----------------------------------------
__global__ void __launch_bounds__(512, 1) attn_kernel(const __half* __restrict__ qp,
                                                      const __half* __restrict__ kvp,
                                                      const __half* __restrict__ bias_mat,
                                                      __half* __restrict__ ao) {
    extern __shared__ char smraw[];
    __half* Ksm = (__half*)smraw;            // 2 x 64 x 40
    __half* Vsm = Ksm + 2 * 2560;            // 2 x 64 x 40
    __half* Ost = Vsm + 2 * 2560;            // 256 x 40

    const int bx = blockIdx.x;
    const int h = bx & 7, b = bx >> 3;
    const int tid = threadIdx.x, w = tid >> 5, lane = tid & 31;
    const int LDKV = 2 * DIMX;
    const int q0 = w * 16;

    const __half* Kb = kvp + ((size_t)b * NK) * LDKV + h * DH;
    const __half* Vb = Kb + DIMX;
    const uint32_t sK = (uint32_t)__cvta_generic_to_shared(Ksm);
    const uint32_t sV = (uint32_t)__cvta_generic_to_shared(Vsm);
    const uint32_t sO = (uint32_t)__cvta_generic_to_shared(Ost);

    auto prefKV = [&](int chunk, int buf) {
        int t = tid & 255;
        int r = t >> 2, c8 = t & 3;
        const __half* src = ((tid < 256) ? Kb : Vb) + (size_t)(chunk * 64 + r) * LDKV + c8 * 8;
        uint32_t dst = ((tid < 256) ? sK : sV) + (buf * 2560 + r * 40 + c8 * 8) * 2;
        cp16(dst, src);
    };
    prefKV(0, 0); cp_commit();

    {
        const __half* qsrc = qp + ((size_t)(b * NQ + q0)) * DIMX + h * DH;
#pragma unroll
        for (int i = lane; i < 64; i += 32) {
            int r = i >> 2, c8 = i & 3;
            *(uint4*)(Ost + (q0 + r) * 40 + c8 * 8) =
                *(const uint4*)(qsrc + (size_t)r * DIMX + c8 * 8);
        }
        __syncwarp();
    }
    uint32_t qa[2][4];
    {
        int t = lane >> 3, wi = lane & 7;
        int qrow = q0 + (t & 1) * 8 + wi;
        int qcolbase = (t >> 1) * 8;
#pragma unroll
        for (int kt = 0; kt < 2; kt++)
            ldsm4(sO + (qrow * 40 + qcolbase + kt * 16) * 2,
                  qa[kt][0], qa[kt][1], qa[kt][2], qa[kt][3]);
    }

    const int r1 = q0 + (lane >> 2);
    const int r2 = r1 + 8;
    float m1 = -1e30f, m2 = -1e30f, s1 = 0.f, s2 = 0.f;
    float o[4][4];
#pragma unroll
    for (int j = 0; j < 4; j++)
#pragma unroll
        for (int e = 0; e < 4; e++) o[j][e] = 0.f;

    const __half* bm = bias_mat + (size_t)h * NQ * NK;
    const __half* b1base = bm + (size_t)r1 * NK + (lane & 3) * 2;
    const __half* b2base = bm + (size_t)r2 * NK + (lane & 3) * 2;

    const int kt_t = lane >> 3, kt_wi = lane & 7;
    const int krow_off = (kt_t >> 1) * 8 + kt_wi;
    const int kcol_off = (kt_t & 1) * 8;
    const int vrow_off = (kt_t & 1) * 8 + kt_wi;
    const int vcol_off = (kt_t >> 1) * 8;

    for (int c = 0; c < 9; c++) {
        cp_wait<0>();
        __syncthreads();
        if (c < 8) { prefKV(c + 1, (c + 1) & 1); cp_commit(); }

        const uint32_t sKc = sK + ((c & 1) * 2560) * 2;
        const uint32_t sVc = sV + ((c & 1) * 2560) * 2;

        float s[8][4];
#pragma unroll
        for (int j = 0; j < 8; j++)
#pragma unroll
            for (int e = 0; e < 4; e++) s[j][e] = 0.f;

#pragma unroll
        for (int g = 0; g < 4; g++) {
#pragma unroll
            for (int kt = 0; kt < 2; kt++) {
                uint32_t b0, b1, b2, b3;
                ldsm4(sKc + ((g * 16 + krow_off) * 40 + kt * 16 + kcol_off) * 2,
                      b0, b1, b2, b3);
                mma16816(s[2 * g],     qa[kt][0], qa[kt][1], qa[kt][2], qa[kt][3], b0, b1);
                mma16816(s[2 * g + 1], qa[kt][0], qa[kt][1], qa[kt][2], qa[kt][3], b2, b3);
            }
        }

        const __half* b1p = b1base + c * 64;
        const __half* b2p = b2base + c * 64;
        float cm1 = -1e30f, cm2 = -1e30f;
#pragma unroll
        for (int j = 0; j < 8; j++) {
            __half2 bb1 = *(const __half2*)(b1p + j * 8);
            __half2 bb2 = *(const __half2*)(b2p + j * 8);
            s[j][0] = fmaf(s[j][0], SCALE, __low2float(bb1));
            s[j][1] = fmaf(s[j][1], SCALE, __high2float(bb1));
            s[j][2] = fmaf(s[j][2], SCALE, __low2float(bb2));
            s[j][3] = fmaf(s[j][3], SCALE, __high2float(bb2));
            cm1 = fmaxf(cm1, fmaxf(s[j][0], s[j][1]));
            cm2 = fmaxf(cm2, fmaxf(s[j][2], s[j][3]));
        }
        cm1 = fmaxf(cm1, __shfl_xor_sync(0xffffffffu, cm1, 1));
        cm1 = fmaxf(cm1, __shfl_xor_sync(0xffffffffu, cm1, 2));
        cm2 = fmaxf(cm2, __shfl_xor_sync(0xffffffffu, cm2, 1));
        cm2 = fmaxf(cm2, __shfl_xor_sync(0xffffffffu, cm2, 2));

        float m1n = fmaxf(m1, cm1), m2n = fmaxf(m2, cm2);
        float a1 = __expf(m1 - m1n), a2 = __expf(m2 - m2n);
        float sum1 = 0.f, sum2 = 0.f;
#pragma unroll
        for (int j = 0; j < 8; j++) {
            s[j][0] = __expf(s[j][0] - m1n);
            s[j][1] = __expf(s[j][1] - m1n);
            s[j][2] = __expf(s[j][2] - m2n);
            s[j][3] = __expf(s[j][3] - m2n);
            sum1 += s[j][0] + s[j][1];
            sum2 += s[j][2] + s[j][3];
        }
        sum1 += __shfl_xor_sync(0xffffffffu, sum1, 1);
        sum1 += __shfl_xor_sync(0xffffffffu, sum1, 2);
        sum2 += __shfl_xor_sync(0xffffffffu, sum2, 1);
        sum2 += __shfl_xor_sync(0xffffffffu, sum2, 2);
        s1 = s1 * a1 + sum1;
        s2 = s2 * a2 + sum2;
        m1 = m1n;
        m2 = m2n;

#pragma unroll
        for (int j = 0; j < 4; j++) {
            o[j][0] *= a1; o[j][1] *= a1;
            o[j][2] *= a2; o[j][3] *= a2;
        }

#pragma unroll
        for (int kt = 0; kt < 4; kt++) {
            uint32_t pa0 = h2pack(s[2 * kt][0], s[2 * kt][1]);
            uint32_t pa1 = h2pack(s[2 * kt][2], s[2 * kt][3]);
            uint32_t pa2 = h2pack(s[2 * kt + 1][0], s[2 * kt + 1][1]);
            uint32_t pa3 = h2pack(s[2 * kt + 1][2], s[2 * kt + 1][3]);
#pragma unroll
            for (int vg = 0; vg < 2; vg++) {
                uint32_t b0, b1, b2, b3;
                ldsm4t(sVc + ((kt * 16 + vrow_off) * 40 + vg * 16 + vcol_off) * 2,
                       b0, b1, b2, b3);
                mma16816(o[vg * 2],     pa0, pa1, pa2, pa3, b0, b1);
                mma16816(o[vg * 2 + 1], pa0, pa1, pa2, pa3, b2, b3);
            }
        }
        __syncthreads();
    }

    float inv1 = 1.f / s1, inv2 = 1.f / s2;
#pragma unroll
    for (int j = 0; j < 4; j++) {
        *(__half2*)(Ost + r1 * 40 + j * 8 + (lane & 3) * 2) =
            __floats2half2_rn(o[j][0] * inv1, o[j][1] * inv1);
        *(__half2*)(Ost + r2 * 40 + j * 8 + (lane & 3) * 2) =
            __floats2half2_rn(o[j][2] * inv2, o[j][3] * inv2);
    }
    __syncthreads();
    {
        int row = tid >> 1, seg = tid & 1;
        uint4* dst = (uint4*)(ao + ((size_t)(b * NQ + row)) * DIMX + h * DH + seg * 16);
        dst[0] = *(uint4*)(Ost + row * 40 + seg * 16);
        dst[1] = *(uint4*)(Ost + row * 40 + seg * 16 + 8);
    }
}

// ---------------- launch ----------------------------------------------------
extern "C" void kernel_launch(void* const* d_in, const int* in_sizes, int n_in,
                              void* d_out, int out_size) {
    const float* q_w = (const float*)d_in[0];
    const float* kv_w = (const float*)d_in[1];
    const float* q_W = (const float*)d_in[2];
    const float* q_b = (const float*)d_in[3];
    const float* kv_W = (const float*)d_in[4];
    const float* kv_b = (const float*)d_in[5];
    const float* proj_W = (const float*)d_in[6];
    const float* proj_b = (const float*)d_in[7];
    const float* bias_table = (const float*)d_in[8];
    const int* rel_index = (const int*)d_in[9];
    float* out = (float*)d_out;

    __half *qwh, *kvwh, *wqh, *wkvh, *wph, *qph, *kvph, *biash, *aoh;
    cudaGetSymbolAddress((void**)&qwh, g_qwh);
    cudaGetSymbolAddress((void**)&kvwh, g_kvwh);
    cudaGetSymbolAddress((void**)&wqh, g_wqh);
    cudaGetSymbolAddress((void**)&wkvh, g_wkvh);
    cudaGetSymbolAddress((void**)&wph, g_wph);
    cudaGetSymbolAddress((void**)&qph, g_qph);
    cudaGetSymbolAddress((void**)&kvph, g_kvph);
    cudaGetSymbolAddress((void**)&biash, g_biash);
    cudaGetSymbolAddress((void**)&aoh, g_aoh);

    const int GEMM_SMEM = (2 * A_STG + 2 * B_STG) * 2;           // 71680 B
    const int ATTN_SMEM = (2 * 2560 + 2 * 2560 + 256 * 40) * 2;  // 40960 B

    cudaFuncSetAttribute(gemm_mma<1>, cudaFuncAttributeMaxDynamicSharedMemorySize, GEMM_SMEM);
    cudaFuncSetAttribute(gemm_mma<0>, cudaFuncAttributeMaxDynamicSharedMemorySize, GEMM_SMEM);

    f2h<<<(4194304 + 255) / 256, 256>>>((const float4*)q_w, qwh, 4194304);
    f2h<<<(9437184 + 255) / 256, 256>>>((const float4*)kv_w, kvwh, 9437184);
    f2h<<<(16384 + 255) / 256, 256>>>((const float4*)q_W, wqh, 16384);
    f2h<<<(32768 + 255) / 256, 256>>>((const float4*)kv_W, wkvh, 32768);
    f2h<<<(16384 + 255) / 256, 256>>>((const float4*)proj_W, wph, 16384);
    bias_gather<<<(NQ * NK + 255) / 256, 256>>>(bias_table, rel_index, biash);

    gemm_mma<1><<<dim3(2, 512), 256, GEMM_SMEM>>>(qwh, wqh, q_b, qph, 256);
    gemm_mma<1><<<dim3(4, 1152), 256, GEMM_SMEM>>>(kvwh, wkvh, kv_b, kvph, 512);
    attn_kernel<<<BATCH * HEADS, 512, ATTN_SMEM>>>(qph, kvph, biash, aoh);
    gemm_mma<0><<<dim3(2, 512), 256, GEMM_SMEM>>>(aoh, wph, proj_b, out, 256);
}

// round 15
// speedup vs baseline: 1.5049x; 1.0178x over previous
#include <cuda_runtime.h>
#include <cuda_fp16.h>
#include <cstdint>

#define DIMX   256
#define HEADS  8
#define BATCH  256
#define NQ     256
#define NK     576
#define DH     32
#define SCALE  0.17677669529663687f

// ---------------- scratch (device globals: no allocations allowed) ----------
__device__ __align__(16) __half g_qwh[(size_t)BATCH * NQ * DIMX];
__device__ __align__(16) __half g_kvwh[(size_t)BATCH * NK * DIMX];
__device__ __align__(16) __half g_wqh[DIMX * DIMX];
__device__ __align__(16) __half g_wkvh[DIMX * 2 * DIMX];
__device__ __align__(16) __half g_wph[DIMX * DIMX];
__device__ __align__(16) __half g_qph[(size_t)BATCH * NQ * DIMX];
__device__ __align__(16) __half g_kvph[(size_t)BATCH * NK * 2 * DIMX];
__device__ __align__(16) __half g_biash[(size_t)HEADS * NQ * NK];
__device__ __align__(16) __half g_aoh[(size_t)BATCH * NQ * DIMX];

__device__ __forceinline__ void cp16(uint32_t dst, const void* src) {
    asm volatile("cp.async.cg.shared.global [%0], [%1], 16;\n" :: "r"(dst), "l"(src));
}
__device__ __forceinline__ void cp_commit() {
    asm volatile("cp.async.commit_group;\n");
}
template <int N>
__device__ __forceinline__ void cp_wait() {
    asm volatile("cp.async.wait_group %0;\n" :: "n"(N));
}
__device__ __forceinline__ void ldsm4(uint32_t addr, uint32_t& r0, uint32_t& r1,
                                      uint32_t& r2, uint32_t& r3) {
    asm volatile("ldmatrix.sync.aligned.m8n8.x4.shared.b16 {%0,%1,%2,%3}, [%4];"
                 : "=r"(r0), "=r"(r1), "=r"(r2), "=r"(r3) : "r"(addr));
}
__device__ __forceinline__ void ldsm4t(uint32_t addr, uint32_t& r0, uint32_t& r1,
                                       uint32_t& r2, uint32_t& r3) {
    asm volatile("ldmatrix.sync.aligned.m8n8.x4.trans.shared.b16 {%0,%1,%2,%3}, [%4];"
                 : "=r"(r0), "=r"(r1), "=r"(r2), "=r"(r3) : "r"(addr));
}
__device__ __forceinline__ void mma16816(float* c, uint32_t a0, uint32_t a1, uint32_t a2,
                                         uint32_t a3, uint32_t b0, uint32_t b1) {
    asm volatile(
        "mma.sync.aligned.m16n8k16.row.col.f32.f16.f16.f32 "
        "{%0,%1,%2,%3},{%4,%5,%6,%7},{%8,%9},{%0,%1,%2,%3};"
        : "+f"(c[0]), "+f"(c[1]), "+f"(c[2]), "+f"(c[3])
        : "r"(a0), "r"(a1), "r"(a2), "r"(a3), "r"(b0), "r"(b1));
}
__device__ __forceinline__ uint32_t h2pack(float lo, float hi) {
    __half2 h = __floats2half2_rn(lo, hi);
    return *reinterpret_cast<uint32_t*>(&h);
}

// ---------------- f32 -> f16 conversion ------------------------------------
__global__ void f2h(const float4* __restrict__ src, __half* __restrict__ dst, int n4) {
    int i = blockIdx.x * 256 + threadIdx.x;
    if (i >= n4) return;
    float4 v = src[i];
    __half2* d = (__half2*)dst;
    d[i * 2 + 0] = __floats2half2_rn(v.x, v.y);
    d[i * 2 + 1] = __floats2half2_rn(v.z, v.w);
}

// ---------------- gather relative-position bias -> half [H,Nq,Nk] ----------
__global__ void bias_gather(const float* __restrict__ table,
                            const int* __restrict__ rel,
                            __half* __restrict__ bias_mat) {
    int p = blockIdx.x * 256 + threadIdx.x;
    if (p >= NQ * NK) return;
    int idx = rel[p];
    const float4* t4 = reinterpret_cast<const float4*>(table + (size_t)idx * 8);
    float4 a = t4[0];
    float4 b = t4[1];
    const int PL = NQ * NK;
    bias_mat[0 * PL + p] = __float2half(a.x);
    bias_mat[1 * PL + p] = __float2half(a.y);
    bias_mat[2 * PL + p] = __float2half(a.z);
    bias_mat[3 * PL + p] = __float2half(a.w);
    bias_mat[4 * PL + p] = __float2half(b.x);
    bias_mat[5 * PL + p] = __float2half(b.y);
    bias_mat[6 * PL + p] = __float2half(b.z);
    bias_mat[7 * PL + p] = __float2half(b.w);
}

#define LDA 72
#define LDB 136
#define A_STG (128 * LDA)     // 9216 halves
#define B_STG (64 * LDB)      // 8704 halves

// ---------------- merged q-proj + kv-proj GEMM (half out, staged stores) ----
// 1D grid: blocks [0,4608) = kv (bm<1152, bn<4, N=512); [4608,5632) = q
__global__ void __launch_bounds__(256, 2) gemm_qkv(const __half* __restrict__ qA,
                                                   const __half* __restrict__ kA,
                                                   const __half* __restrict__ qW,
                                                   const __half* __restrict__ kW,
                                                   const float* __restrict__ qb,
                                                   const float* __restrict__ kb,
                                                   __half* __restrict__ qC,
                                                   __half* __restrict__ kC) {
    extern __shared__ char smraw[];
    __half* As = (__half*)smraw;          // 2 x 128 x 72
    __half* Bs = As + 2 * A_STG;          // 2 x 64 x 136

    const int tid = threadIdx.x;
    const int w = tid >> 5, lane = tid & 31;
    const int wm = w >> 2, wn = w & 3;    // 2 x 4 warp grid

    // decode job (kv blocks first: longer job starts first, short q fills tail)
    int bid = blockIdx.x;
    const __half *Ab, *Wb;
    const float* bias;
    __half* C;
    int N, bm, bn;
    if (bid < 4608) {
        N = 512; bm = bid >> 2; bn = bid & 3;
        Ab = kA + (size_t)bm * 128 * 256;
        Wb = kW + bn * 128;
        bias = kb; C = kC;
    } else {
        int t2 = bid - 4608;
        N = 256; bm = t2 >> 1; bn = t2 & 1;
        Ab = qA + (size_t)bm * 128 * 256;
        Wb = qW + bn * 128;
        bias = qb; C = qC;
    }

    const uint32_t sA = (uint32_t)__cvta_generic_to_shared(As);
    const uint32_t sB = (uint32_t)__cvta_generic_to_shared(Bs);

    auto pref = [&](int kt, int stg) {
#pragma unroll
        for (int it = 0; it < 4; it++) {          // A: 1024 chunks of 8 halves
            int i = it * 256 + tid;
            int r = i >> 3, c8 = i & 7;
            cp16(sA + (stg * A_STG + r * LDA + c8 * 8) * 2,
                 Ab + (size_t)r * 256 + kt * 64 + c8 * 8);
        }
#pragma unroll
        for (int it = 0; it < 4; it++) {          // B: 1024 chunks
            int i = it * 256 + tid;
            int r = i >> 4, c8 = i & 15;
            cp16(sB + (stg * B_STG + r * LDB + c8 * 8) * 2,
                 Wb + (size_t)(kt * 64 + r) * N + c8 * 8);
        }
        cp_commit();
    };

    pref(0, 0);
    pref(1, 1);

    float acc[4][4][4];
#pragma unroll
    for (int mt = 0; mt < 4; mt++)
#pragma unroll
        for (int nj = 0; nj < 4; nj++)
#pragma unroll
            for (int e = 0; e < 4; e++) acc[mt][nj][e] = 0.f;

    const int t = lane >> 3, wi = lane & 7;
    const int arow = (t & 1) * 8 + wi, acol = (t >> 1) * 8;
    const int brow = (t & 1) * 8 + wi, bcol = (t >> 1) * 8;

#pragma unroll
    for (int kt = 0; kt < 4; kt++) {
        if (kt < 3) cp_wait<1>(); else cp_wait<0>();
        __syncthreads();

        const uint32_t sAc = sA + ((kt & 1) * A_STG) * 2;
        const uint32_t sBc = sB + ((kt & 1) * B_STG) * 2;

#pragma unroll
        for (int kk = 0; kk < 4; kk++) {
            uint32_t a[4][4];
#pragma unroll
            for (int mt = 0; mt < 4; mt++)
                ldsm4(sAc + ((wm * 64 + mt * 16 + arow) * LDA + kk * 16 + acol) * 2,
                      a[mt][0], a[mt][1], a[mt][2], a[mt][3]);
#pragma unroll
            for (int ng = 0; ng < 2; ng++) {
                uint32_t b0, b1, b2, b3;
                ldsm4t(sBc + ((kk * 16 + brow) * LDB + wn * 32 + ng * 16 + bcol) * 2,
                       b0, b1, b2, b3);
#pragma unroll
                for (int mt = 0; mt < 4; mt++) {
                    mma16816(acc[mt][ng * 2],     a[mt][0], a[mt][1], a[mt][2], a[mt][3], b0, b1);
                    mma16816(acc[mt][ng * 2 + 1], a[mt][0], a[mt][1], a[mt][2], a[mt][3], b2, b3);
                }
            }
        }
        if (kt < 2) {
            __syncthreads();
            pref(kt + 2, kt & 1);
        }
    }

    // epilogue: stage half tile in smem (conflict-free), then coalesced stores
    __syncthreads();                     // all warps done with smem stages
    __half* Cs = (__half*)smraw;         // 128 x 136 halves = 34816 B
    const int rr = lane >> 2, cc = (lane & 3) * 2;
#pragma unroll
    for (int nj = 0; nj < 4; nj++) {
        int coll = wn * 32 + nj * 8 + cc;
        float b0 = bias[bn * 128 + coll], b1 = bias[bn * 128 + coll + 1];
#pragma unroll
        for (int mt = 0; mt < 4; mt++) {
            int rowl = wm * 64 + mt * 16 + rr;
            float* c = acc[mt][nj];
            *(__half2*)(Cs + rowl * 136 + coll) = __floats2half2_rn(c[0] + b0, c[1] + b1);
            *(__half2*)(Cs + (rowl + 8) * 136 + coll) = __floats2half2_rn(c[2] + b0, c[3] + b1);
        }
    }
    __syncthreads();
#pragma unroll
    for (int it = 0; it < 8; it++) {
        int idx = it * 256 + tid;        // 2048 chunks = 128 rows x 16 chunks
        int r = idx >> 4, c16 = idx & 15;
        *(uint4*)(C + (size_t)(bm * 128 + r) * N + bn * 128 + c16 * 8) =
            *(uint4*)(Cs + r * 136 + c16 * 8);
    }
}

// ---------------- proj GEMM (f32 out, direct stores — already coalesced) ----
__global__ void __launch_bounds__(256, 2) gemm_proj(const __half* __restrict__ A,
                                                    const __half* __restrict__ W,
                                                    const float* __restrict__ bias,
                                                    float* __restrict__ C) {
    extern __shared__ char smraw[];
    __half* As = (__half*)smraw;
    __half* Bs = As + 2 * A_STG;
    const int N = 256;

    const int tid = threadIdx.x;
    const int w = tid >> 5, lane = tid & 31;
    const int wm = w >> 2, wn = w & 3;
    const int bm = blockIdx.y, bn = blockIdx.x;

    const __half* Ab = A + (size_t)bm * 128 * 256;
    const __half* Wb = W + bn * 128;
    const uint32_t sA = (uint32_t)__cvta_generic_to_shared(As);
    const uint32_t sB = (uint32_t)__cvta_generic_to_shared(Bs);

    auto pref = [&](int kt, int stg) {
#pragma unroll
        for (int it = 0; it < 4; it++) {
            int i = it * 256 + tid;
            int r = i >> 3, c8 = i & 7;
            cp16(sA + (stg * A_STG + r * LDA + c8 * 8) * 2,
                 Ab + (size_t)r * 256 + kt * 64 + c8 * 8);
        }
#pragma unroll
        for (int it = 0; it < 4; it++) {
            int i = it * 256 + tid;
            int r = i >> 4, c8 = i & 15;
            cp16(sB + (stg * B_STG + r * LDB + c8 * 8) * 2,
                 Wb + (size_t)(kt * 64 + r) * N + c8 * 8);
        }
        cp_commit();
    };

    pref(0, 0);
    pref(1, 1);

    float acc[4][4][4];
#pragma unroll
    for (int mt = 0; mt < 4; mt++)
#pragma unroll
        for (int nj = 0; nj < 4; nj++)
#pragma unroll
            for (int e = 0; e < 4; e++) acc[mt][nj][e] = 0.f;

    const int t = lane >> 3, wi = lane & 7;
    const int arow = (t & 1) * 8 + wi, acol = (t >> 1) * 8;
    const int brow = (t & 1) * 8 + wi, bcol = (t >> 1) * 8;

#pragma unroll
    for (int kt = 0; kt < 4; kt++) {
        if (kt < 3) cp_wait<1>(); else cp_wait<0>();
        __syncthreads();

        const uint32_t sAc = sA + ((kt & 1) * A_STG) * 2;
        const uint32_t sBc = sB + ((kt & 1) * B_STG) * 2;

#pragma unroll
        for (int kk = 0; kk < 4; kk++) {
            uint32_t a[4][4];
#pragma unroll
            for (int mt = 0; mt < 4; mt++)
                ldsm4(sAc + ((wm * 64 + mt * 16 + arow) * LDA + kk * 16 + acol) * 2,
                      a[mt][0], a[mt][1], a[mt][2], a[mt][3]);
#pragma unroll
            for (int ng = 0; ng < 2; ng++) {
                uint32_t b0, b1, b2, b3;
                ldsm4t(sBc + ((kk * 16 + brow) * LDB + wn * 32 + ng * 16 + bcol) * 2,
                       b0, b1, b2, b3);
#pragma unroll
                for (int mt = 0; mt < 4; mt++) {
                    mma16816(acc[mt][ng * 2],     a[mt][0], a[mt][1], a[mt][2], a[mt][3], b0, b1);
                    mma16816(acc[mt][ng * 2 + 1], a[mt][0], a[mt][1], a[mt][2], a[mt][3], b2, b3);
                }
            }
        }
        if (kt < 2) {
            __syncthreads();
            pref(kt + 2, kt & 1);
        }
    }

    const int rr = lane >> 2, cc = (lane & 3) * 2;
#pragma unroll
    for (int nj = 0; nj < 4; nj++) {
        int col = bn * 128 + wn * 32 + nj * 8 + cc;
        float b0 = bias[col], b1 = bias[col + 1];
#pragma unroll
        for (int mt = 0; mt < 4; mt++) {
            int row1 = bm * 128 + wm * 64 + mt * 16 + rr;
            float* c = acc[mt][nj];
            *(float2*)(C + (size_t)row1 * N + col) = make_float2(c[0] + b0, c[1] + b1);
            *(float2*)(C + (size_t)(row1 + 8) * N + col) = make_float2(c[2] + b0, c[3] + b1);
        }
    }
}

// ---------------- flash attention v3 (unchanged champion) --------------------
__global__ void __launch_bounds__(512, 1) attn_kernel(const __half* __restrict__ qp,
                                                      const __half* __restrict__ kvp,
                                                      const __half* __restrict__ bias_mat,
                                                      __half* __restrict__ ao) {
    extern __shared__ char smraw[];
    __half* Ksm = (__half*)smraw;            // 2 x 64 x 40
    __half* Vsm = Ksm + 2 * 2560;            // 2 x 64 x 40
    __half* Ost = Vsm + 2 * 2560;            // 256 x 40

    const int bx = blockIdx.x;
    const int h = bx & 7, b = bx >> 3;
    const int tid = threadIdx.x, w = tid >> 5, lane = tid & 31;
    const int LDKV = 2 * DIMX;
    const int q0 = w * 16;

    const __half* Kb = kvp + ((size_t)b * NK) * LDKV + h * DH;
    const __half* Vb = Kb + DIMX;
    const uint32_t sK = (uint32_t)__cvta_generic_to_shared(Ksm);
    const uint32_t sV = (uint32_t)__cvta_generic_to_shared(Vsm);
    const uint32_t sO = (uint32_t)__cvta_generic_to_shared(Ost);

    auto prefKV = [&](int chunk, int buf) {
        int t = tid & 255;
        int r = t >> 2, c8 = t & 3;
        const __half* src = ((tid < 256) ? Kb : Vb) + (size_t)(chunk * 64 + r) * LDKV + c8 * 8;
        uint32_t dst = ((tid < 256) ? sK : sV) + (buf * 2560 + r * 40 + c8 * 8) * 2;
        cp16(dst, src);
    };
    prefKV(0, 0); cp_commit();

    {
        const __half* qsrc = qp + ((size_t)(b * NQ + q0)) * DIMX + h * DH;
#pragma unroll
        for (int i = lane; i < 64; i += 32) {
            int r = i >> 2, c8 = i & 3;
            *(uint4*)(Ost + (q0 + r) * 40 + c8 * 8) =
                *(const uint4*)(qsrc + (size_t)r * DIMX + c8 * 8);
        }
        __syncwarp();
    }
    uint32_t qa[2][4];
    {
        int t = lane >> 3, wi = lane & 7;
        int qrow = q0 + (t & 1) * 8 + wi;
        int qcolbase = (t >> 1) * 8;
#pragma unroll
        for (int kt = 0; kt < 2; kt++)
            ldsm4(sO + (qrow * 40 + qcolbase + kt * 16) * 2,
                  qa[kt][0], qa[kt][1], qa[kt][2], qa[kt][3]);
    }

    const int r1 = q0 + (lane >> 2);
    const int r2 = r1 + 8;
    float m1 = -1e30f, m2 = -1e30f, s1 = 0.f, s2 = 0.f;
    float o[4][4];
#pragma unroll
    for (int j = 0; j < 4; j++)
#pragma unroll
        for (int e = 0; e < 4; e++) o[j][e] = 0.f;

    const __half* bm = bias_mat + (size_t)h * NQ * NK;
    const __half* b1base = bm + (size_t)r1 * NK + (lane & 3) * 2;
    const __half* b2base = bm + (size_t)r2 * NK + (lane & 3) * 2;

    const int kt_t = lane >> 3, kt_wi = lane & 7;
    const int krow_off = (kt_t >> 1) * 8 + kt_wi;
    const int kcol_off = (kt_t & 1) * 8;
    const int vrow_off = (kt_t & 1) * 8 + kt_wi;
    const int vcol_off = (kt_t >> 1) * 8;

    for (int c = 0; c < 9; c++) {
        cp_wait<0>();
        __syncthreads();
        if (c < 8) { prefKV(c + 1, (c + 1) & 1); cp_commit(); }

        const uint32_t sKc = sK + ((c & 1) * 2560) * 2;
        const uint32_t sVc = sV + ((c & 1) * 2560) * 2;

        float s[8][4];
#pragma unroll
        for (int j = 0; j < 8; j++)
#pragma unroll
            for (int e = 0; e < 4; e++) s[j][e] = 0.f;

#pragma unroll
        for (int g = 0; g < 4; g++) {
#pragma unroll
            for (int kt = 0; kt < 2; kt++) {
                uint32_t b0, b1, b2, b3;
                ldsm4(sKc + ((g * 16 + krow_off) * 40 + kt * 16 + kcol_off) * 2,
                      b0, b1, b2, b3);
                mma16816(s[2 * g],     qa[kt][0], qa[kt][1], qa[kt][2], qa[kt][3], b0, b1);
                mma16816(s[2 * g + 1], qa[kt][0], qa[kt][1], qa[kt][2], qa[kt][3], b2, b3);
            }
        }

        const __half* b1p = b1base + c * 64;
        const __half* b2p = b2base + c * 64;
        float cm1 = -1e30f, cm2 = -1e30f;
#pragma unroll
        for (int j = 0; j < 8; j++) {
            __half2 bb1 = *(const __half2*)(b1p + j * 8);
            __half2 bb2 = *(const __half2*)(b2p + j * 8);
            s[j][0] = fmaf(s[j][0], SCALE, __low2float(bb1));
            s[j][1] = fmaf(s[j][1], SCALE, __high2float(bb1));
            s[j][2] = fmaf(s[j][2], SCALE, __low2float(bb2));
            s[j][3] = fmaf(s[j][3], SCALE, __high2float(bb2));
            cm1 = fmaxf(cm1, fmaxf(s[j][0], s[j][1]));
            cm2 = fmaxf(cm2, fmaxf(s[j][2], s[j][3]));
        }
        cm1 = fmaxf(cm1, __shfl_xor_sync(0xffffffffu, cm1, 1));
        cm1 = fmaxf(cm1, __shfl_xor_sync(0xffffffffu, cm1, 2));
        cm2 = fmaxf(cm2, __shfl_xor_sync(0xffffffffu, cm2, 1));
        cm2 = fmaxf(cm2, __shfl_xor_sync(0xffffffffu, cm2, 2));

        float m1n = fmaxf(m1, cm1), m2n = fmaxf(m2, cm2);
        float a1 = __expf(m1 - m1n), a2 = __expf(m2 - m2n);
        float sum1 = 0.f, sum2 = 0.f;
#pragma unroll
        for (int j = 0; j < 8; j++) {
            s[j][0] = __expf(s[j][0] - m1n);
            s[j][1] = __expf(s[j][1] - m1n);
            s[j][2] = __expf(s[j][2] - m2n);
            s[j][3] = __expf(s[j][3] - m2n);
            sum1 += s[j][0] + s[j][1];
            sum2 += s[j][2] + s[j][3];
        }
        sum1 += __shfl_xor_sync(0xffffffffu, sum1, 1);
        sum1 += __shfl_xor_sync(0xffffffffu, sum1, 2);
        sum2 += __shfl_xor_sync(0xffffffffu, sum2, 1);
        sum2 += __shfl_xor_sync(0xffffffffu, sum2, 2);
        s1 = s1 * a1 + sum1;
        s2 = s2 * a2 + sum2;
        m1 = m1n;
        m2 = m2n;

#pragma unroll
        for (int j = 0; j < 4; j++) {
            o[j][0] *= a1; o[j][1] *= a1;
            o[j][2] *= a2; o[j][3] *= a2;
        }

#pragma unroll
        for (int kt = 0; kt < 4; kt++) {
            uint32_t pa0 = h2pack(s[2 * kt][0], s[2 * kt][1]);
            uint32_t pa1 = h2pack(s[2 * kt][2], s[2 * kt][3]);
            uint32_t pa2 = h2pack(s[2 * kt + 1][0], s[2 * kt + 1][1]);
            uint32_t pa3 = h2pack(s[2 * kt + 1][2], s[2 * kt + 1][3]);
#pragma unroll
            for (int vg = 0; vg < 2; vg++) {
                uint32_t b0, b1, b2, b3;
                ldsm4t(sVc + ((kt * 16 + vrow_off) * 40 + vg * 16 + vcol_off) * 2,
                       b0, b1, b2, b3);
                mma16816(o[vg * 2],     pa0, pa1, pa2, pa3, b0, b1);
                mma16816(o[vg * 2 + 1], pa0, pa1, pa2, pa3, b2, b3);
            }
        }
        __syncthreads();
    }

    float inv1 = 1.f / s1, inv2 = 1.f / s2;
#pragma unroll
    for (int j = 0; j < 4; j++) {
        *(__half2*)(Ost + r1 * 40 + j * 8 + (lane & 3) * 2) =
            __floats2half2_rn(o[j][0] * inv1, o[j][1] * inv1);
        *(__half2*)(Ost + r2 * 40 + j * 8 + (lane & 3) * 2) =
            __floats2half2_rn(o[j][2] * inv2, o[j][3] * inv2);
    }
    __syncthreads();
    {
        int row = tid >> 1, seg = tid & 1;
        uint4* dst = (uint4*)(ao + ((size_t)(b * NQ + row)) * DIMX + h * DH + seg * 16);
        dst[0] = *(uint4*)(Ost + row * 40 + seg * 16);
        dst[1] = *(uint4*)(Ost + row * 40 + seg * 16 + 8);
    }
}

// ---------------- launch ----------------------------------------------------
extern "C" void kernel_launch(void* const* d_in, const int* in_sizes, int n_in,
                              void* d_out, int out_size) {
    const float* q_w = (const float*)d_in[0];
    const float* kv_w = (const float*)d_in[1];
    const float* q_W = (const float*)d_in[2];
    const float* q_b = (const float*)d_in[3];
    const float* kv_W = (const float*)d_in[4];
    const float* kv_b = (const float*)d_in[5];
    const float* proj_W = (const float*)d_in[6];
    const float* proj_b = (const float*)d_in[7];
    const float* bias_table = (const float*)d_in[8];
    const int* rel_index = (const int*)d_in[9];
    float* out = (float*)d_out;

    __half *qwh, *kvwh, *wqh, *wkvh, *wph, *qph, *kvph, *biash, *aoh;
    cudaGetSymbolAddress((void**)&qwh, g_qwh);
    cudaGetSymbolAddress((void**)&kvwh, g_kvwh);
    cudaGetSymbolAddress((void**)&wqh, g_wqh);
    cudaGetSymbolAddress((void**)&wkvh, g_wkvh);
    cudaGetSymbolAddress((void**)&wph, g_wph);
    cudaGetSymbolAddress((void**)&qph, g_qph);
    cudaGetSymbolAddress((void**)&kvph, g_kvph);
    cudaGetSymbolAddress((void**)&biash, g_biash);
    cudaGetSymbolAddress((void**)&aoh, g_aoh);

    const int GEMM_SMEM = (2 * A_STG + 2 * B_STG) * 2;           // 71680 B
    const int ATTN_SMEM = (2 * 2560 + 2 * 2560 + 256 * 40) * 2;  // 40960 B

    cudaFuncSetAttribute(gemm_qkv, cudaFuncAttributeMaxDynamicSharedMemorySize, GEMM_SMEM);
    cudaFuncSetAttribute(gemm_proj, cudaFuncAttributeMaxDynamicSharedMemorySize, GEMM_SMEM);

    f2h<<<(4194304 + 255) / 256, 256>>>((const float4*)q_w, qwh, 4194304);
    f2h<<<(9437184 + 255) / 256, 256>>>((const float4*)kv_w, kvwh, 9437184);
    f2h<<<(16384 + 255) / 256, 256>>>((const float4*)q_W, wqh, 16384);
    f2h<<<(32768 + 255) / 256, 256>>>((const float4*)kv_W, wkvh, 32768);
    f2h<<<(16384 + 255) / 256, 256>>>((const float4*)proj_W, wph, 16384);
    bias_gather<<<(NQ * NK + 255) / 256, 256>>>(bias_table, rel_index, biash);

    gemm_qkv<<<5632, 256, GEMM_SMEM>>>(qwh, kvwh, wqh, wkvh, q_b, kv_b, qph, kvph);
    attn_kernel<<<BATCH * HEADS, 512, ATTN_SMEM>>>(qph, kvph, biash, aoh);
    gemm_proj<<<dim3(2, 512), 256, GEMM_SMEM>>>(aoh, wph, proj_b, out);
}

// round 16
// speedup vs baseline: 1.7551x; 1.1663x over previous
#include <cuda_runtime.h>
#include <cuda_fp16.h>
#include <cstdint>

#define DIMX   256
#define HEADS  8
#define BATCH  256
#define NQ     256
#define NK     576
#define DH     32
#define SCALE  0.17677669529663687f

// ---------------- scratch (device globals: no allocations allowed) ----------
__device__ __align__(16) __half g_qwh[(size_t)BATCH * NQ * DIMX];
__device__ __align__(16) __half g_kvwh[(size_t)BATCH * NK * DIMX];
__device__ __align__(16) __half g_wqh[DIMX * DIMX];
__device__ __align__(16) __half g_wkvh[DIMX * 2 * DIMX];
__device__ __align__(16) __half g_wph[DIMX * DIMX];
__device__ __align__(16) __half g_qph[(size_t)BATCH * NQ * DIMX];
__device__ __align__(16) __half g_kvph[(size_t)BATCH * NK * 2 * DIMX];
__device__ __align__(16) __half g_biash[(size_t)HEADS * NQ * NK];
__device__ __align__(16) __half g_aoh[(size_t)BATCH * NQ * DIMX];

__device__ __forceinline__ void cp16(uint32_t dst, const void* src) {
    asm volatile("cp.async.cg.shared.global [%0], [%1], 16;\n" :: "r"(dst), "l"(src));
}
__device__ __forceinline__ void cp_commit() {
    asm volatile("cp.async.commit_group;\n");
}
template <int N>
__device__ __forceinline__ void cp_wait() {
    asm volatile("cp.async.wait_group %0;\n" :: "n"(N));
}
__device__ __forceinline__ void ldsm4(uint32_t addr, uint32_t& r0, uint32_t& r1,
                                      uint32_t& r2, uint32_t& r3) {
    asm volatile("ldmatrix.sync.aligned.m8n8.x4.shared.b16 {%0,%1,%2,%3}, [%4];"
                 : "=r"(r0), "=r"(r1), "=r"(r2), "=r"(r3) : "r"(addr));
}
__device__ __forceinline__ void ldsm4t(uint32_t addr, uint32_t& r0, uint32_t& r1,
                                       uint32_t& r2, uint32_t& r3) {
    asm volatile("ldmatrix.sync.aligned.m8n8.x4.trans.shared.b16 {%0,%1,%2,%3}, [%4];"
                 : "=r"(r0), "=r"(r1), "=r"(r2), "=r"(r3) : "r"(addr));
}
__device__ __forceinline__ void mma16816(float* c, uint32_t a0, uint32_t a1, uint32_t a2,
                                         uint32_t a3, uint32_t b0, uint32_t b1) {
    asm volatile(
        "mma.sync.aligned.m16n8k16.row.col.f32.f16.f16.f32 "
        "{%0,%1,%2,%3},{%4,%5,%6,%7},{%8,%9},{%0,%1,%2,%3};"
        : "+f"(c[0]), "+f"(c[1]), "+f"(c[2]), "+f"(c[3])
        : "r"(a0), "r"(a1), "r"(a2), "r"(a3), "r"(b0), "r"(b1));
}
__device__ __forceinline__ uint32_t h2pack(float lo, float hi) {
    __half2 h = __floats2half2_rn(lo, hi);
    return *reinterpret_cast<uint32_t*>(&h);
}

// ---------------- f32 -> f16 conversion ------------------------------------
__global__ void f2h(const float4* __restrict__ src, __half* __restrict__ dst, int n4) {
    int i = blockIdx.x * 256 + threadIdx.x;
    if (i >= n4) return;
    float4 v = src[i];
    __half2* d = (__half2*)dst;
    d[i * 2 + 0] = __floats2half2_rn(v.x, v.y);
    d[i * 2 + 1] = __floats2half2_rn(v.z, v.w);
}

// ---------------- gather relative-position bias -> half [H,Nq,Nk] ----------
__global__ void bias_gather(const float* __restrict__ table,
                            const int* __restrict__ rel,
                            __half* __restrict__ bias_mat) {
    int p = blockIdx.x * 256 + threadIdx.x;
    if (p >= NQ * NK) return;
    int idx = rel[p];
    const float4* t4 = reinterpret_cast<const float4*>(table + (size_t)idx * 8);
    float4 a = t4[0];
    float4 b = t4[1];
    const int PL = NQ * NK;
    bias_mat[0 * PL + p] = __float2half(a.x);
    bias_mat[1 * PL + p] = __float2half(a.y);
    bias_mat[2 * PL + p] = __float2half(a.z);
    bias_mat[3 * PL + p] = __float2half(a.w);
    bias_mat[4 * PL + p] = __float2half(b.x);
    bias_mat[5 * PL + p] = __float2half(b.y);
    bias_mat[6 * PL + p] = __float2half(b.z);
    bias_mat[7 * PL + p] = __float2half(b.w);
}

#define LDA 72
#define LDB 136
#define A_STG (128 * LDA)     // 9216 halves
#define B_STG (64 * LDB)      // 8704 halves

// ---------------- merged q-proj + kv-proj GEMM (half out, staged stores) ----
// 1D grid: blocks [0,4608) = kv (bm<1152, bn<4, N=512); [4608,5632) = q
__global__ void __launch_bounds__(256, 2) gemm_qkv(const __half* __restrict__ qA,
                                                   const __half* __restrict__ kA,
                                                   const __half* __restrict__ qW,
                                                   const __half* __restrict__ kW,
                                                   const float* __restrict__ qb,
                                                   const float* __restrict__ kb,
                                                   __half* __restrict__ qC,
                                                   __half* __restrict__ kC) {
    extern __shared__ char smraw[];
    __half* As = (__half*)smraw;          // 2 x 128 x 72
    __half* Bs = As + 2 * A_STG;          // 2 x 64 x 136

    const int tid = threadIdx.x;
    const int w = tid >> 5, lane = tid & 31;
    const int wm = w >> 2, wn = w & 3;    // 2 x 4 warp grid

    // decode job (kv blocks first: longer job starts first, short q fills tail)
    int bid = blockIdx.x;
    const __half *Ab, *Wb;
    const float* bias;
    __half* C;
    int N, bm, bn;
    if (bid < 4608) {
        N = 512; bm = bid >> 2; bn = bid & 3;
        Ab = kA + (size_t)bm * 128 * 256;
        Wb = kW + bn * 128;
        bias = kb; C = kC;
    } else {
        int t2 = bid - 4608;
        N = 256; bm = t2 >> 1; bn = t2 & 1;
        Ab = qA + (size_t)bm * 128 * 256;
        Wb = qW + bn * 128;
        bias = qb; C = qC;
    }

    const uint32_t sA = (uint32_t)__cvta_generic_to_shared(As);
    const uint32_t sB = (uint32_t)__cvta_generic_to_shared(Bs);

    auto pref = [&](int kt, int stg) {
#pragma unroll
        for (int it = 0; it < 4; it++) {          // A: 1024 chunks of 8 halves
            int i = it * 256 + tid;
            int r = i >> 3, c8 = i & 7;
            cp16(sA + (stg * A_STG + r * LDA + c8 * 8) * 2,
                 Ab + (size_t)r * 256 + kt * 64 + c8 * 8);
        }
#pragma unroll
        for (int it = 0; it < 4; it++) {          // B: 1024 chunks
            int i = it * 256 + tid;
            int r = i >> 4, c8 = i & 15;
            cp16(sB + (stg * B_STG + r * LDB + c8 * 8) * 2,
                 Wb + (size_t)(kt * 64 + r) * N + c8 * 8);
        }
        cp_commit();
    };

    pref(0, 0);
    pref(1, 1);

    float acc[4][4][4];
#pragma unroll
    for (int mt = 0; mt < 4; mt++)
#pragma unroll
        for (int nj = 0; nj < 4; nj++)
#pragma unroll
            for (int e = 0; e < 4; e++) acc[mt][nj][e] = 0.f;

    const int t = lane >> 3, wi = lane & 7;
    const int arow = (t & 1) * 8 + wi, acol = (t >> 1) * 8;
    const int brow = (t & 1) * 8 + wi, bcol = (t >> 1) * 8;

#pragma unroll
    for (int kt = 0; kt < 4; kt++) {
        if (kt < 3) cp_wait<1>(); else cp_wait<0>();
        __syncthreads();

        const uint32_t sAc = sA + ((kt & 1) * A_STG) * 2;
        const uint32_t sBc = sB + ((kt & 1) * B_STG) * 2;

#pragma unroll
        for (int kk = 0; kk < 4; kk++) {
            uint32_t a[4][4];
#pragma unroll
            for (int mt = 0; mt < 4; mt++)
                ldsm4(sAc + ((wm * 64 + mt * 16 + arow) * LDA + kk * 16 + acol) * 2,
                      a[mt][0], a[mt][1], a[mt][2], a[mt][3]);
#pragma unroll
            for (int ng = 0; ng < 2; ng++) {
                uint32_t b0, b1, b2, b3;
                ldsm4t(sBc + ((kk * 16 + brow) * LDB + wn * 32 + ng * 16 + bcol) * 2,
                       b0, b1, b2, b3);
#pragma unroll
                for (int mt = 0; mt < 4; mt++) {
                    mma16816(acc[mt][ng * 2],     a[mt][0], a[mt][1], a[mt][2], a[mt][3], b0, b1);
                    mma16816(acc[mt][ng * 2 + 1], a[mt][0], a[mt][1], a[mt][2], a[mt][3], b2, b3);
                }
            }
        }
        if (kt < 2) {
            __syncthreads();
            pref(kt + 2, kt & 1);
        }
    }

    // epilogue: stage half tile in smem (conflict-free), then coalesced stores
    __syncthreads();                     // all warps done with smem stages
    __half* Cs = (__half*)smraw;         // 128 x 136 halves = 34816 B
    const int rr = lane >> 2, cc = (lane & 3) * 2;
#pragma unroll
    for (int nj = 0; nj < 4; nj++) {
        int coll = wn * 32 + nj * 8 + cc;
        float b0 = bias[bn * 128 + coll], b1 = bias[bn * 128 + coll + 1];
#pragma unroll
        for (int mt = 0; mt < 4; mt++) {
            int rowl = wm * 64 + mt * 16 + rr;
            float* c = acc[mt][nj];
            *(__half2*)(Cs + rowl * 136 + coll) = __floats2half2_rn(c[0] + b0, c[1] + b1);
            *(__half2*)(Cs + (rowl + 8) * 136 + coll) = __floats2half2_rn(c[2] + b0, c[3] + b1);
        }
    }
    __syncthreads();
#pragma unroll
    for (int it = 0; it < 8; it++) {
        int idx = it * 256 + tid;        // 2048 chunks = 128 rows x 16 chunks
        int r = idx >> 4, c16 = idx & 15;
        *(uint4*)(C + (size_t)(bm * 128 + r) * N + bn * 128 + c16 * 8) =
            *(uint4*)(Cs + r * 136 + c16 * 8);
    }
}

// ---------------- proj GEMM (f32 out, direct stores — already coalesced) ----
__global__ void __launch_bounds__(256, 2) gemm_proj(const __half* __restrict__ A,
                                                    const __half* __restrict__ W,
                                                    const float* __restrict__ bias,
                                                    float* __restrict__ C) {
    extern __shared__ char smraw[];
    __half* As = (__half*)smraw;
    __half* Bs = As + 2 * A_STG;
    const int N = 256;

    const int tid = threadIdx.x;
    const int w = tid >> 5, lane = tid & 31;
    const int wm = w >> 2, wn = w & 3;
    const int bm = blockIdx.y, bn = blockIdx.x;

    const __half* Ab = A + (size_t)bm * 128 * 256;
    const __half* Wb = W + bn * 128;
    const uint32_t sA = (uint32_t)__cvta_generic_to_shared(As);
    const uint32_t sB = (uint32_t)__cvta_generic_to_shared(Bs);

    auto pref = [&](int kt, int stg) {
#pragma unroll
        for (int it = 0; it < 4; it++) {
            int i = it * 256 + tid;
            int r = i >> 3, c8 = i & 7;
            cp16(sA + (stg * A_STG + r * LDA + c8 * 8) * 2,
                 Ab + (size_t)r * 256 + kt * 64 + c8 * 8);
        }
#pragma unroll
        for (int it = 0; it < 4; it++) {
            int i = it * 256 + tid;
            int r = i >> 4, c8 = i & 15;
            cp16(sB + (stg * B_STG + r * LDB + c8 * 8) * 2,
                 Wb + (size_t)(kt * 64 + r) * N + c8 * 8);
        }
        cp_commit();
    };

    pref(0, 0);
    pref(1, 1);

    float acc[4][4][4];
#pragma unroll
    for (int mt = 0; mt < 4; mt++)
#pragma unroll
        for (int nj = 0; nj < 4; nj++)
#pragma unroll
            for (int e = 0; e < 4; e++) acc[mt][nj][e] = 0.f;

    const int t = lane >> 3, wi = lane & 7;
    const int arow = (t & 1) * 8 + wi, acol = (t >> 1) * 8;
    const int brow = (t & 1) * 8 + wi, bcol = (t >> 1) * 8;

#pragma unroll
    for (int kt = 0; kt < 4; kt++) {
        if (kt < 3) cp_wait<1>(); else cp_wait<0>();
        __syncthreads();

        const uint32_t sAc = sA + ((kt & 1) * A_STG) * 2;
        const uint32_t sBc = sB + ((kt & 1) * B_STG) * 2;

#pragma unroll
        for (int kk = 0; kk < 4; kk++) {
            uint32_t a[4][4];
#pragma unroll
            for (int mt = 0; mt < 4; mt++)
                ldsm4(sAc + ((wm * 64 + mt * 16 + arow) * LDA + kk * 16 + acol) * 2,
                      a[mt][0], a[mt][1], a[mt][2], a[mt][3]);
#pragma unroll
            for (int ng = 0; ng < 2; ng++) {
                uint32_t b0, b1, b2, b3;
                ldsm4t(sBc + ((kk * 16 + brow) * LDB + wn * 32 + ng * 16 + bcol) * 2,
                       b0, b1, b2, b3);
#pragma unroll
                for (int mt = 0; mt < 4; mt++) {
                    mma16816(acc[mt][ng * 2],     a[mt][0], a[mt][1], a[mt][2], a[mt][3], b0, b1);
                    mma16816(acc[mt][ng * 2 + 1], a[mt][0], a[mt][1], a[mt][2], a[mt][3], b2, b3);
                }
            }
        }
        if (kt < 2) {
            __syncthreads();
            pref(kt + 2, kt & 1);
        }
    }

    const int rr = lane >> 2, cc = (lane & 3) * 2;
#pragma unroll
    for (int nj = 0; nj < 4; nj++) {
        int col = bn * 128 + wn * 32 + nj * 8 + cc;
        float b0 = bias[col], b1 = bias[col + 1];
#pragma unroll
        for (int mt = 0; mt < 4; mt++) {
            int row1 = bm * 128 + wm * 64 + mt * 16 + rr;
            float* c = acc[mt][nj];
            *(float2*)(C + (size_t)row1 * N + col) = make_float2(c[0] + b0, c[1] + b1);
            *(float2*)(C + (size_t)(row1 + 8) * N + col) = make_float2(c[2] + b0, c[3] + b1);
        }
    }
}

// ---------------- flash attention v5: 2 CTAs per (b,h), 256 threads ---------
// CTA handles 128 q rows (8 warps x 16); 2 CTAs/SM hide barrier/mem stalls
__global__ void __launch_bounds__(256, 2) attn_kernel(const __half* __restrict__ qp,
                                                      const __half* __restrict__ kvp,
                                                      const __half* __restrict__ bias_mat,
                                                      __half* __restrict__ ao) {
    extern __shared__ char smraw[];
    __half* Ksm = (__half*)smraw;            // 2 x 64 x 40
    __half* Vsm = Ksm + 2 * 2560;            // 2 x 64 x 40
    __half* Ost = Vsm + 2 * 2560;            // 128 x 40

    const int bx = blockIdx.x;
    const int hf = bx & 1, h = (bx >> 1) & 7, b = bx >> 4;
    const int tid = threadIdx.x, w = tid >> 5, lane = tid & 31;
    const int LDKV = 2 * DIMX;
    const int ql0 = w * 16;                  // local q row base (0..112)
    const int qg0 = hf * 128 + ql0;          // global q row base

    const __half* Kb = kvp + ((size_t)b * NK) * LDKV + h * DH;
    const __half* Vb = Kb + DIMX;
    const uint32_t sK = (uint32_t)__cvta_generic_to_shared(Ksm);
    const uint32_t sV = (uint32_t)__cvta_generic_to_shared(Vsm);
    const uint32_t sO = (uint32_t)__cvta_generic_to_shared(Ost);

    // each thread loads one K chunk and one V chunk (64 rows x 4 x 16B each)
    auto prefKV = [&](int chunk, int buf) {
        int r = tid >> 2, c8 = tid & 3;
        const __half* src = Kb + (size_t)(chunk * 64 + r) * LDKV + c8 * 8;
        cp16(sK + (buf * 2560 + r * 40 + c8 * 8) * 2, src);
        cp16(sV + (buf * 2560 + r * 40 + c8 * 8) * 2, src + DIMX);
    };
    prefKV(0, 0); cp_commit();

    // stage warp's Q (16 rows x 32 halves) into its Ost region, ldsm to frags
    {
        const __half* qsrc = qp + ((size_t)(b * NQ + qg0)) * DIMX + h * DH;
#pragma unroll
        for (int i = lane; i < 64; i += 32) {      // 16 rows x 4 uint4
            int r = i >> 2, c8 = i & 3;
            *(uint4*)(Ost + (ql0 + r) * 40 + c8 * 8) =
                *(const uint4*)(qsrc + (size_t)r * DIMX + c8 * 8);
        }
        __syncwarp();
    }
    uint32_t qa[2][4];
    {
        int t = lane >> 3, wi = lane & 7;
        int qrow = ql0 + (t & 1) * 8 + wi;
        int qcolbase = (t >> 1) * 8;
#pragma unroll
        for (int kt = 0; kt < 2; kt++)
            ldsm4(sO + (qrow * 40 + qcolbase + kt * 16) * 2,
                  qa[kt][0], qa[kt][1], qa[kt][2], qa[kt][3]);
    }

    const int r1 = qg0 + (lane >> 2);        // global q rows for this thread
    const int r2 = r1 + 8;
    float m1 = -1e30f, m2 = -1e30f, s1 = 0.f, s2 = 0.f;
    float o[4][4];
#pragma unroll
    for (int j = 0; j < 4; j++)
#pragma unroll
        for (int e = 0; e < 4; e++) o[j][e] = 0.f;

    const __half* bm = bias_mat + (size_t)h * NQ * NK;
    const __half* b1base = bm + (size_t)r1 * NK + (lane & 3) * 2;
    const __half* b2base = bm + (size_t)r2 * NK + (lane & 3) * 2;

    const int kt_t = lane >> 3, kt_wi = lane & 7;
    const int krow_off = (kt_t >> 1) * 8 + kt_wi;
    const int kcol_off = (kt_t & 1) * 8;
    const int vrow_off = (kt_t & 1) * 8 + kt_wi;
    const int vcol_off = (kt_t >> 1) * 8;

    for (int c = 0; c < 9; c++) {
        cp_wait<0>();
        __syncthreads();
        if (c < 8) { prefKV(c + 1, (c + 1) & 1); cp_commit(); }

        const uint32_t sKc = sK + ((c & 1) * 2560) * 2;
        const uint32_t sVc = sV + ((c & 1) * 2560) * 2;

        float s[8][4];
#pragma unroll
        for (int j = 0; j < 8; j++)
#pragma unroll
            for (int e = 0; e < 4; e++) s[j][e] = 0.f;

#pragma unroll
        for (int g = 0; g < 4; g++) {
#pragma unroll
            for (int kt = 0; kt < 2; kt++) {
                uint32_t b0, b1, b2, b3;
                ldsm4(sKc + ((g * 16 + krow_off) * 40 + kt * 16 + kcol_off) * 2,
                      b0, b1, b2, b3);
                mma16816(s[2 * g],     qa[kt][0], qa[kt][1], qa[kt][2], qa[kt][3], b0, b1);
                mma16816(s[2 * g + 1], qa[kt][0], qa[kt][1], qa[kt][2], qa[kt][3], b2, b3);
            }
        }

        const __half* b1p = b1base + c * 64;
        const __half* b2p = b2base + c * 64;
        float cm1 = -1e30f, cm2 = -1e30f;
#pragma unroll
        for (int j = 0; j < 8; j++) {
            __half2 bb1 = *(const __half2*)(b1p + j * 8);
            __half2 bb2 = *(const __half2*)(b2p + j * 8);
            s[j][0] = fmaf(s[j][0], SCALE, __low2float(bb1));
            s[j][1] = fmaf(s[j][1], SCALE, __high2float(bb1));
            s[j][2] = fmaf(s[j][2], SCALE, __low2float(bb2));
            s[j][3] = fmaf(s[j][3], SCALE, __high2float(bb2));
            cm1 = fmaxf(cm1, fmaxf(s[j][0], s[j][1]));
            cm2 = fmaxf(cm2, fmaxf(s[j][2], s[j][3]));
        }
        cm1 = fmaxf(cm1, __shfl_xor_sync(0xffffffffu, cm1, 1));
        cm1 = fmaxf(cm1, __shfl_xor_sync(0xffffffffu, cm1, 2));
        cm2 = fmaxf(cm2, __shfl_xor_sync(0xffffffffu, cm2, 1));
        cm2 = fmaxf(cm2, __shfl_xor_sync(0xffffffffu, cm2, 2));

        float m1n = fmaxf(m1, cm1), m2n = fmaxf(m2, cm2);
        float a1 = __expf(m1 - m1n), a2 = __expf(m2 - m2n);
        float sum1 = 0.f, sum2 = 0.f;
#pragma unroll
        for (int j = 0; j < 8; j++) {
            s[j][0] = __expf(s[j][0] - m1n);
            s[j][1] = __expf(s[j][1] - m1n);
            s[j][2] = __expf(s[j][2] - m2n);
            s[j][3] = __expf(s[j][3] - m2n);
            sum1 += s[j][0] + s[j][1];
            sum2 += s[j][2] + s[j][3];
        }
        sum1 += __shfl_xor_sync(0xffffffffu, sum1, 1);
        sum1 += __shfl_xor_sync(0xffffffffu, sum1, 2);
        sum2 += __shfl_xor_sync(0xffffffffu, sum2, 1);
        sum2 += __shfl_xor_sync(0xffffffffu, sum2, 2);
        s1 = s1 * a1 + sum1;
        s2 = s2 * a2 + sum2;
        m1 = m1n;
        m2 = m2n;

#pragma unroll
        for (int j = 0; j < 4; j++) {
            o[j][0] *= a1; o[j][1] *= a1;
            o[j][2] *= a2; o[j][3] *= a2;
        }

#pragma unroll
        for (int kt = 0; kt < 4; kt++) {
            uint32_t pa0 = h2pack(s[2 * kt][0], s[2 * kt][1]);
            uint32_t pa1 = h2pack(s[2 * kt][2], s[2 * kt][3]);
            uint32_t pa2 = h2pack(s[2 * kt + 1][0], s[2 * kt + 1][1]);
            uint32_t pa3 = h2pack(s[2 * kt + 1][2], s[2 * kt + 1][3]);
#pragma unroll
            for (int vg = 0; vg < 2; vg++) {
                uint32_t b0, b1, b2, b3;
                ldsm4t(sVc + ((kt * 16 + vrow_off) * 40 + vg * 16 + vcol_off) * 2,
                       b0, b1, b2, b3);
                mma16816(o[vg * 2],     pa0, pa1, pa2, pa3, b0, b1);
                mma16816(o[vg * 2 + 1], pa0, pa1, pa2, pa3, b2, b3);
            }
        }
        __syncthreads();
    }

    // normalize, stage to smem (local rows), coalesced store
    float inv1 = 1.f / s1, inv2 = 1.f / s2;
    const int rl1 = ql0 + (lane >> 2), rl2 = rl1 + 8;
#pragma unroll
    for (int j = 0; j < 4; j++) {
        *(__half2*)(Ost + rl1 * 40 + j * 8 + (lane & 3) * 2) =
            __floats2half2_rn(o[j][0] * inv1, o[j][1] * inv1);
        *(__half2*)(Ost + rl2 * 40 + j * 8 + (lane & 3) * 2) =
            __floats2half2_rn(o[j][2] * inv2, o[j][3] * inv2);
    }
    __syncthreads();
    {
        int rowl = tid >> 1, seg = tid & 1;   // 128 rows x 2 segs
        uint4* dst = (uint4*)(ao + ((size_t)(b * NQ + hf * 128 + rowl)) * DIMX + h * DH + seg * 16);
        dst[0] = *(uint4*)(Ost + rowl * 40 + seg * 16);
        dst[1] = *(uint4*)(Ost + rowl * 40 + seg * 16 + 8);
    }
}

// ---------------- launch ----------------------------------------------------
extern "C" void kernel_launch(void* const* d_in, const int* in_sizes, int n_in,
                              void* d_out, int out_size) {
    const float* q_w = (const float*)d_in[0];
    const float* kv_w = (const float*)d_in[1];
    const float* q_W = (const float*)d_in[2];
    const float* q_b = (const float*)d_in[3];
    const float* kv_W = (const float*)d_in[4];
    const float* kv_b = (const float*)d_in[5];
    const float* proj_W = (const float*)d_in[6];
    const float* proj_b = (const float*)d_in[7];
    const float* bias_table = (const float*)d_in[8];
    const int* rel_index = (const int*)d_in[9];
    float* out = (float*)d_out;

    __half *qwh, *kvwh, *wqh, *wkvh, *wph, *qph, *kvph, *biash, *aoh;
    cudaGetSymbolAddress((void**)&qwh, g_qwh);
    cudaGetSymbolAddress((void**)&kvwh, g_kvwh);
    cudaGetSymbolAddress((void**)&wqh, g_wqh);
    cudaGetSymbolAddress((void**)&wkvh, g_wkvh);
    cudaGetSymbolAddress((void**)&wph, g_wph);
    cudaGetSymbolAddress((void**)&qph, g_qph);
    cudaGetSymbolAddress((void**)&kvph, g_kvph);
    cudaGetSymbolAddress((void**)&biash, g_biash);
    cudaGetSymbolAddress((void**)&aoh, g_aoh);

    const int GEMM_SMEM = (2 * A_STG + 2 * B_STG) * 2;           // 71680 B
    const int ATTN_SMEM = (2 * 2560 + 2 * 2560 + 128 * 40) * 2;  // 30720 B

    cudaFuncSetAttribute(gemm_qkv, cudaFuncAttributeMaxDynamicSharedMemorySize, GEMM_SMEM);
    cudaFuncSetAttribute(gemm_proj, cudaFuncAttributeMaxDynamicSharedMemorySize, GEMM_SMEM);
    cudaFuncSetAttribute(attn_kernel, cudaFuncAttributeMaxDynamicSharedMemorySize, ATTN_SMEM);

    f2h<<<(4194304 + 255) / 256, 256>>>((const float4*)q_w, qwh, 4194304);
    f2h<<<(9437184 + 255) / 256, 256>>>((const float4*)kv_w, kvwh, 9437184);
    f2h<<<(16384 + 255) / 256, 256>>>((const float4*)q_W, wqh, 16384);
    f2h<<<(32768 + 255) / 256, 256>>>((const float4*)kv_W, wkvh, 32768);
    f2h<<<(16384 + 255) / 256, 256>>>((const float4*)proj_W, wph, 16384);
    bias_gather<<<(NQ * NK + 255) / 256, 256>>>(bias_table, rel_index, biash);

    gemm_qkv<<<5632, 256, GEMM_SMEM>>>(qwh, kvwh, wqh, wkvh, q_b, kv_b, qph, kvph);
    attn_kernel<<<BATCH * HEADS * 2, 256, ATTN_SMEM>>>(qph, kvph, biash, aoh);
    gemm_proj<<<dim3(2, 512), 256, GEMM_SMEM>>>(aoh, wph, proj_b, out);
}

// round 17
// speedup vs baseline: 1.8190x; 1.0364x over previous
#include <cuda_runtime.h>
#include <cuda_fp16.h>
#include <cstdint>

#define DIMX   256
#define HEADS  8
#define BATCH  256
#define NQ     256
#define NK     576
#define DH     32
#define SCALE  0.17677669529663687f

// ---------------- scratch (device globals: no allocations allowed) ----------
__device__ __align__(16) __half g_qwh[(size_t)BATCH * NQ * DIMX];
__device__ __align__(16) __half g_kvwh[(size_t)BATCH * NK * DIMX];
__device__ __align__(16) __half g_wqh[DIMX * DIMX];
__device__ __align__(16) __half g_wkvh[DIMX * 2 * DIMX];
__device__ __align__(16) __half g_wph[DIMX * DIMX];
__device__ __align__(16) __half g_qph[(size_t)BATCH * NQ * DIMX];
__device__ __align__(16) __half g_kvph[(size_t)BATCH * NK * 2 * DIMX];
__device__ __align__(16) __half g_biash[(size_t)HEADS * NQ * NK];
__device__ __align__(16) __half g_aoh[(size_t)BATCH * NQ * DIMX];

__device__ __forceinline__ void cp16(uint32_t dst, const void* src) {
    asm volatile("cp.async.cg.shared.global [%0], [%1], 16;\n" :: "r"(dst), "l"(src));
}
__device__ __forceinline__ void cp_commit() {
    asm volatile("cp.async.commit_group;\n");
}
template <int N>
__device__ __forceinline__ void cp_wait() {
    asm volatile("cp.async.wait_group %0;\n" :: "n"(N));
}
__device__ __forceinline__ void ldsm4(uint32_t addr, uint32_t& r0, uint32_t& r1,
                                      uint32_t& r2, uint32_t& r3) {
    asm volatile("ldmatrix.sync.aligned.m8n8.x4.shared.b16 {%0,%1,%2,%3}, [%4];"
                 : "=r"(r0), "=r"(r1), "=r"(r2), "=r"(r3) : "r"(addr));
}
__device__ __forceinline__ void ldsm4t(uint32_t addr, uint32_t& r0, uint32_t& r1,
                                       uint32_t& r2, uint32_t& r3) {
    asm volatile("ldmatrix.sync.aligned.m8n8.x4.trans.shared.b16 {%0,%1,%2,%3}, [%4];"
                 : "=r"(r0), "=r"(r1), "=r"(r2), "=r"(r3) : "r"(addr));
}
__device__ __forceinline__ void mma16816(float* c, uint32_t a0, uint32_t a1, uint32_t a2,
                                         uint32_t a3, uint32_t b0, uint32_t b1) {
    asm volatile(
        "mma.sync.aligned.m16n8k16.row.col.f32.f16.f16.f32 "
        "{%0,%1,%2,%3},{%4,%5,%6,%7},{%8,%9},{%0,%1,%2,%3};"
        : "+f"(c[0]), "+f"(c[1]), "+f"(c[2]), "+f"(c[3])
        : "r"(a0), "r"(a1), "r"(a2), "r"(a3), "r"(b0), "r"(b1));
}
__device__ __forceinline__ uint32_t h2pack(float lo, float hi) {
    __half2 h = __floats2half2_rn(lo, hi);
    return *reinterpret_cast<uint32_t*>(&h);
}

// ---------------- f32 -> f16 conversion ------------------------------------
__global__ void f2h(const float4* __restrict__ src, __half* __restrict__ dst, int n4) {
    int i = blockIdx.x * 256 + threadIdx.x;
    if (i >= n4) return;
    float4 v = src[i];
    __half2* d = (__half2*)dst;
    d[i * 2 + 0] = __floats2half2_rn(v.x, v.y);
    d[i * 2 + 1] = __floats2half2_rn(v.z, v.w);
}

// ---------------- gather relative-position bias -> half [H,Nq,Nk] ----------
__global__ void bias_gather(const float* __restrict__ table,
                            const int* __restrict__ rel,
                            __half* __restrict__ bias_mat) {
    int p = blockIdx.x * 256 + threadIdx.x;
    if (p >= NQ * NK) return;
    int idx = rel[p];
    const float4* t4 = reinterpret_cast<const float4*>(table + (size_t)idx * 8);
    float4 a = t4[0];
    float4 b = t4[1];
    const int PL = NQ * NK;
    bias_mat[0 * PL + p] = __float2half(a.x);
    bias_mat[1 * PL + p] = __float2half(a.y);
    bias_mat[2 * PL + p] = __float2half(a.z);
    bias_mat[3 * PL + p] = __float2half(a.w);
    bias_mat[4 * PL + p] = __float2half(b.x);
    bias_mat[5 * PL + p] = __float2half(b.y);
    bias_mat[6 * PL + p] = __float2half(b.z);
    bias_mat[7 * PL + p] = __float2half(b.w);
}

#define LDA 72
#define LDB 136
#define A_STG (128 * LDA)     // 9216 halves
#define B_STG (64 * LDB)      // 8704 halves

// ---------------- merged q-proj + kv-proj GEMM (3-stage, half out) ----------
// 1D grid: blocks [0,4608) = kv (bm<1152, bn<4, N=512); [4608,5632) = q
__global__ void __launch_bounds__(256, 2) gemm_qkv(const __half* __restrict__ qA,
                                                   const __half* __restrict__ kA,
                                                   const __half* __restrict__ qW,
                                                   const __half* __restrict__ kW,
                                                   const float* __restrict__ qb,
                                                   const float* __restrict__ kb,
                                                   __half* __restrict__ qC,
                                                   __half* __restrict__ kC) {
    extern __shared__ char smraw[];
    __half* As = (__half*)smraw;          // 3 x 128 x 72
    __half* Bs = As + 3 * A_STG;          // 3 x 64 x 136

    const int tid = threadIdx.x;
    const int w = tid >> 5, lane = tid & 31;
    const int wm = w >> 2, wn = w & 3;    // 2 x 4 warp grid

    int bid = blockIdx.x;
    const __half *Ab, *Wb;
    const float* bias;
    __half* C;
    int N, bm, bn;
    if (bid < 4608) {
        N = 512; bm = bid >> 2; bn = bid & 3;
        Ab = kA + (size_t)bm * 128 * 256;
        Wb = kW + bn * 128;
        bias = kb; C = kC;
    } else {
        int t2 = bid - 4608;
        N = 256; bm = t2 >> 1; bn = t2 & 1;
        Ab = qA + (size_t)bm * 128 * 256;
        Wb = qW + bn * 128;
        bias = qb; C = qC;
    }

    const uint32_t sA = (uint32_t)__cvta_generic_to_shared(As);
    const uint32_t sB = (uint32_t)__cvta_generic_to_shared(Bs);

    auto pref = [&](int kt, int stg) {
#pragma unroll
        for (int it = 0; it < 4; it++) {          // A: 1024 chunks of 8 halves
            int i = it * 256 + tid;
            int r = i >> 3, c8 = i & 7;
            cp16(sA + (stg * A_STG + r * LDA + c8 * 8) * 2,
                 Ab + (size_t)r * 256 + kt * 64 + c8 * 8);
        }
#pragma unroll
        for (int it = 0; it < 4; it++) {          // B: 1024 chunks
            int i = it * 256 + tid;
            int r = i >> 4, c8 = i & 15;
            cp16(sB + (stg * B_STG + r * LDB + c8 * 8) * 2,
                 Wb + (size_t)(kt * 64 + r) * N + c8 * 8);
        }
        cp_commit();
    };

    pref(0, 0);
    pref(1, 1);

    float acc[4][4][4];
#pragma unroll
    for (int mt = 0; mt < 4; mt++)
#pragma unroll
        for (int nj = 0; nj < 4; nj++)
#pragma unroll
            for (int e = 0; e < 4; e++) acc[mt][nj][e] = 0.f;

    const int t = lane >> 3, wi = lane & 7;
    const int arow = (t & 1) * 8 + wi, acol = (t >> 1) * 8;
    const int brow = (t & 1) * 8 + wi, bcol = (t >> 1) * 8;

#pragma unroll
    for (int kt = 0; kt < 4; kt++) {
        if (kt < 3) cp_wait<1>(); else cp_wait<0>();
        __syncthreads();                 // single barrier per k-iter (3 stages)
        if (kt < 2) pref(kt + 2, (kt + 2) % 3);

        const uint32_t sAc = sA + ((kt % 3) * A_STG) * 2;
        const uint32_t sBc = sB + ((kt % 3) * B_STG) * 2;

#pragma unroll
        for (int kk = 0; kk < 4; kk++) {
            uint32_t a[4][4];
#pragma unroll
            for (int mt = 0; mt < 4; mt++)
                ldsm4(sAc + ((wm * 64 + mt * 16 + arow) * LDA + kk * 16 + acol) * 2,
                      a[mt][0], a[mt][1], a[mt][2], a[mt][3]);
#pragma unroll
            for (int ng = 0; ng < 2; ng++) {
                uint32_t b0, b1, b2, b3;
                ldsm4t(sBc + ((kk * 16 + brow) * LDB + wn * 32 + ng * 16 + bcol) * 2,
                       b0, b1, b2, b3);
#pragma unroll
                for (int mt = 0; mt < 4; mt++) {
                    mma16816(acc[mt][ng * 2],     a[mt][0], a[mt][1], a[mt][2], a[mt][3], b0, b1);
                    mma16816(acc[mt][ng * 2 + 1], a[mt][0], a[mt][1], a[mt][2], a[mt][3], b2, b3);
                }
            }
        }
    }

    // epilogue: stage half tile in smem (conflict-free), then coalesced stores
    __syncthreads();
    __half* Cs = (__half*)smraw;         // 128 x 136 halves = 34816 B
    const int rr = lane >> 2, cc = (lane & 3) * 2;
#pragma unroll
    for (int nj = 0; nj < 4; nj++) {
        int coll = wn * 32 + nj * 8 + cc;
        float b0 = bias[bn * 128 + coll], b1 = bias[bn * 128 + coll + 1];
#pragma unroll
        for (int mt = 0; mt < 4; mt++) {
            int rowl = wm * 64 + mt * 16 + rr;
            float* c = acc[mt][nj];
            *(__half2*)(Cs + rowl * 136 + coll) = __floats2half2_rn(c[0] + b0, c[1] + b1);
            *(__half2*)(Cs + (rowl + 8) * 136 + coll) = __floats2half2_rn(c[2] + b0, c[3] + b1);
        }
    }
    __syncthreads();
#pragma unroll
    for (int it = 0; it < 8; it++) {
        int idx = it * 256 + tid;        // 2048 chunks = 128 rows x 16 chunks
        int r = idx >> 4, c16 = idx & 15;
        *(uint4*)(C + (size_t)(bm * 128 + r) * N + bn * 128 + c16 * 8) =
            *(uint4*)(Cs + r * 136 + c16 * 8);
    }
}

// ---------------- proj GEMM (3-stage, f32 out, direct stores) ---------------
__global__ void __launch_bounds__(256, 2) gemm_proj(const __half* __restrict__ A,
                                                    const __half* __restrict__ W,
                                                    const float* __restrict__ bias,
                                                    float* __restrict__ C) {
    extern __shared__ char smraw[];
    __half* As = (__half*)smraw;
    __half* Bs = As + 3 * A_STG;
    const int N = 256;

    const int tid = threadIdx.x;
    const int w = tid >> 5, lane = tid & 31;
    const int wm = w >> 2, wn = w & 3;
    const int bm = blockIdx.y, bn = blockIdx.x;

    const __half* Ab = A + (size_t)bm * 128 * 256;
    const __half* Wb = W + bn * 128;
    const uint32_t sA = (uint32_t)__cvta_generic_to_shared(As);
    const uint32_t sB = (uint32_t)__cvta_generic_to_shared(Bs);

    auto pref = [&](int kt, int stg) {
#pragma unroll
        for (int it = 0; it < 4; it++) {
            int i = it * 256 + tid;
            int r = i >> 3, c8 = i & 7;
            cp16(sA + (stg * A_STG + r * LDA + c8 * 8) * 2,
                 Ab + (size_t)r * 256 + kt * 64 + c8 * 8);
        }
#pragma unroll
        for (int it = 0; it < 4; it++) {
            int i = it * 256 + tid;
            int r = i >> 4, c8 = i & 15;
            cp16(sB + (stg * B_STG + r * LDB + c8 * 8) * 2,
                 Wb + (size_t)(kt * 64 + r) * N + c8 * 8);
        }
        cp_commit();
    };

    pref(0, 0);
    pref(1, 1);

    float acc[4][4][4];
#pragma unroll
    for (int mt = 0; mt < 4; mt++)
#pragma unroll
        for (int nj = 0; nj < 4; nj++)
#pragma unroll
            for (int e = 0; e < 4; e++) acc[mt][nj][e] = 0.f;

    const int t = lane >> 3, wi = lane & 7;
    const int arow = (t & 1) * 8 + wi, acol = (t >> 1) * 8;
    const int brow = (t & 1) * 8 + wi, bcol = (t >> 1) * 8;

#pragma unroll
    for (int kt = 0; kt < 4; kt++) {
        if (kt < 3) cp_wait<1>(); else cp_wait<0>();
        __syncthreads();
        if (kt < 2) pref(kt + 2, (kt + 2) % 3);

        const uint32_t sAc = sA + ((kt % 3) * A_STG) * 2;
        const uint32_t sBc = sB + ((kt % 3) * B_STG) * 2;

#pragma unroll
        for (int kk = 0; kk < 4; kk++) {
            uint32_t a[4][4];
#pragma unroll
            for (int mt = 0; mt < 4; mt++)
                ldsm4(sAc + ((wm * 64 + mt * 16 + arow) * LDA + kk * 16 + acol) * 2,
                      a[mt][0], a[mt][1], a[mt][2], a[mt][3]);
#pragma unroll
            for (int ng = 0; ng < 2; ng++) {
                uint32_t b0, b1, b2, b3;
                ldsm4t(sBc + ((kk * 16 + brow) * LDB + wn * 32 + ng * 16 + bcol) * 2,
                       b0, b1, b2, b3);
#pragma unroll
                for (int mt = 0; mt < 4; mt++) {
                    mma16816(acc[mt][ng * 2],     a[mt][0], a[mt][1], a[mt][2], a[mt][3], b0, b1);
                    mma16816(acc[mt][ng * 2 + 1], a[mt][0], a[mt][1], a[mt][2], a[mt][3], b2, b3);
                }
            }
        }
    }

    const int rr = lane >> 2, cc = (lane & 3) * 2;
#pragma unroll
    for (int nj = 0; nj < 4; nj++) {
        int col = bn * 128 + wn * 32 + nj * 8 + cc;
        float b0 = bias[col], b1 = bias[col + 1];
#pragma unroll
        for (int mt = 0; mt < 4; mt++) {
            int row1 = bm * 128 + wm * 64 + mt * 16 + rr;
            float* c = acc[mt][nj];
            *(float2*)(C + (size_t)row1 * N + col) = make_float2(c[0] + b0, c[1] + b1);
            *(float2*)(C + (size_t)(row1 + 8) * N + col) = make_float2(c[2] + b0, c[3] + b1);
        }
    }
}

// ---------------- flash attention v5 (unchanged champion) -------------------
__global__ void __launch_bounds__(256, 2) attn_kernel(const __half* __restrict__ qp,
                                                      const __half* __restrict__ kvp,
                                                      const __half* __restrict__ bias_mat,
                                                      __half* __restrict__ ao) {
    extern __shared__ char smraw[];
    __half* Ksm = (__half*)smraw;            // 2 x 64 x 40
    __half* Vsm = Ksm + 2 * 2560;            // 2 x 64 x 40
    __half* Ost = Vsm + 2 * 2560;            // 128 x 40

    const int bx = blockIdx.x;
    const int hf = bx & 1, h = (bx >> 1) & 7, b = bx >> 4;
    const int tid = threadIdx.x, w = tid >> 5, lane = tid & 31;
    const int LDKV = 2 * DIMX;
    const int ql0 = w * 16;
    const int qg0 = hf * 128 + ql0;

    const __half* Kb = kvp + ((size_t)b * NK) * LDKV + h * DH;
    const __half* Vb = Kb + DIMX;
    const uint32_t sK = (uint32_t)__cvta_generic_to_shared(Ksm);
    const uint32_t sV = (uint32_t)__cvta_generic_to_shared(Vsm);
    const uint32_t sO = (uint32_t)__cvta_generic_to_shared(Ost);

    auto prefKV = [&](int chunk, int buf) {
        int r = tid >> 2, c8 = tid & 3;
        const __half* src = Kb + (size_t)(chunk * 64 + r) * LDKV + c8 * 8;
        cp16(sK + (buf * 2560 + r * 40 + c8 * 8) * 2, src);
        cp16(sV + (buf * 2560 + r * 40 + c8 * 8) * 2, src + DIMX);
    };
    prefKV(0, 0); cp_commit();

    {
        const __half* qsrc = qp + ((size_t)(b * NQ + qg0)) * DIMX + h * DH;
#pragma unroll
        for (int i = lane; i < 64; i += 32) {
            int r = i >> 2, c8 = i & 3;
            *(uint4*)(Ost + (ql0 + r) * 40 + c8 * 8) =
                *(const uint4*)(qsrc + (size_t)r * DIMX + c8 * 8);
        }
        __syncwarp();
    }
    uint32_t qa[2][4];
    {
        int t = lane >> 3, wi = lane & 7;
        int qrow = ql0 + (t & 1) * 8 + wi;
        int qcolbase = (t >> 1) * 8;
#pragma unroll
        for (int kt = 0; kt < 2; kt++)
            ldsm4(sO + (qrow * 40 + qcolbase + kt * 16) * 2,
                  qa[kt][0], qa[kt][1], qa[kt][2], qa[kt][3]);
    }

    const int r1 = qg0 + (lane >> 2);
    const int r2 = r1 + 8;
    float m1 = -1e30f, m2 = -1e30f, s1 = 0.f, s2 = 0.f;
    float o[4][4];
#pragma unroll
    for (int j = 0; j < 4; j++)
#pragma unroll
        for (int e = 0; e < 4; e++) o[j][e] = 0.f;

    const __half* bm = bias_mat + (size_t)h * NQ * NK;
    const __half* b1base = bm + (size_t)r1 * NK + (lane & 3) * 2;
    const __half* b2base = bm + (size_t)r2 * NK + (lane & 3) * 2;

    const int kt_t = lane >> 3, kt_wi = lane & 7;
    const int krow_off = (kt_t >> 1) * 8 + kt_wi;
    const int kcol_off = (kt_t & 1) * 8;
    const int vrow_off = (kt_t & 1) * 8 + kt_wi;
    const int vcol_off = (kt_t >> 1) * 8;

    for (int c = 0; c < 9; c++) {
        cp_wait<0>();
        __syncthreads();
        if (c < 8) { prefKV(c + 1, (c + 1) & 1); cp_commit(); }

        const uint32_t sKc = sK + ((c & 1) * 2560) * 2;
        const uint32_t sVc = sV + ((c & 1) * 2560) * 2;

        float s[8][4];
#pragma unroll
        for (int j = 0; j < 8; j++)
#pragma unroll
            for (int e = 0; e < 4; e++) s[j][e] = 0.f;

#pragma unroll
        for (int g = 0; g < 4; g++) {
#pragma unroll
            for (int kt = 0; kt < 2; kt++) {
                uint32_t b0, b1, b2, b3;
                ldsm4(sKc + ((g * 16 + krow_off) * 40 + kt * 16 + kcol_off) * 2,
                      b0, b1, b2, b3);
                mma16816(s[2 * g],     qa[kt][0], qa[kt][1], qa[kt][2], qa[kt][3], b0, b1);
                mma16816(s[2 * g + 1], qa[kt][0], qa[kt][1], qa[kt][2], qa[kt][3], b2, b3);
            }
        }

        const __half* b1p = b1base + c * 64;
        const __half* b2p = b2base + c * 64;
        float cm1 = -1e30f, cm2 = -1e30f;
#pragma unroll
        for (int j = 0; j < 8; j++) {
            __half2 bb1 = *(const __half2*)(b1p + j * 8);
            __half2 bb2 = *(const __half2*)(b2p + j * 8);
            s[j][0] = fmaf(s[j][0], SCALE, __low2float(bb1));
            s[j][1] = fmaf(s[j][1], SCALE, __high2float(bb1));
            s[j][2] = fmaf(s[j][2], SCALE, __low2float(bb2));
            s[j][3] = fmaf(s[j][3], SCALE, __high2float(bb2));
            cm1 = fmaxf(cm1, fmaxf(s[j][0], s[j][1]));
            cm2 = fmaxf(cm2, fmaxf(s[j][2], s[j][3]));
        }
        cm1 = fmaxf(cm1, __shfl_xor_sync(0xffffffffu, cm1, 1));
        cm1 = fmaxf(cm1, __shfl_xor_sync(0xffffffffu, cm1, 2));
        cm2 = fmaxf(cm2, __shfl_xor_sync(0xffffffffu, cm2, 1));
        cm2 = fmaxf(cm2, __shfl_xor_sync(0xffffffffu, cm2, 2));

        float m1n = fmaxf(m1, cm1), m2n = fmaxf(m2, cm2);
        float a1 = __expf(m1 - m1n), a2 = __expf(m2 - m2n);
        float sum1 = 0.f, sum2 = 0.f;
#pragma unroll
        for (int j = 0; j < 8; j++) {
            s[j][0] = __expf(s[j][0] - m1n);
            s[j][1] = __expf(s[j][1] - m1n);
            s[j][2] = __expf(s[j][2] - m2n);
            s[j][3] = __expf(s[j][3] - m2n);
            sum1 += s[j][0] + s[j][1];
            sum2 += s[j][2] + s[j][3];
        }
        sum1 += __shfl_xor_sync(0xffffffffu, sum1, 1);
        sum1 += __shfl_xor_sync(0xffffffffu, sum1, 2);
        sum2 += __shfl_xor_sync(0xffffffffu, sum2, 1);
        sum2 += __shfl_xor_sync(0xffffffffu, sum2, 2);
        s1 = s1 * a1 + sum1;
        s2 = s2 * a2 + sum2;
        m1 = m1n;
        m2 = m2n;

#pragma unroll
        for (int j = 0; j < 4; j++) {
            o[j][0] *= a1; o[j][1] *= a1;
            o[j][2] *= a2; o[j][3] *= a2;
        }

#pragma unroll
        for (int kt = 0; kt < 4; kt++) {
            uint32_t pa0 = h2pack(s[2 * kt][0], s[2 * kt][1]);
            uint32_t pa1 = h2pack(s[2 * kt][2], s[2 * kt][3]);
            uint32_t pa2 = h2pack(s[2 * kt + 1][0], s[2 * kt + 1][1]);
            uint32_t pa3 = h2pack(s[2 * kt + 1][2], s[2 * kt + 1][3]);
#pragma unroll
            for (int vg = 0; vg < 2; vg++) {
                uint32_t b0, b1, b2, b3;
                ldsm4t(sVc + ((kt * 16 + vrow_off) * 40 + vg * 16 + vcol_off) * 2,
                       b0, b1, b2, b3);
                mma16816(o[vg * 2],     pa0, pa1, pa2, pa3, b0, b1);
                mma16816(o[vg * 2 + 1], pa0, pa1, pa2, pa3, b2, b3);
            }
        }
        __syncthreads();
    }

    float inv1 = 1.f / s1, inv2 = 1.f / s2;
    const int rl1 = ql0 + (lane >> 2), rl2 = rl1 + 8;
#pragma unroll
    for (int j = 0; j < 4; j++) {
        *(__half2*)(Ost + rl1 * 40 + j * 8 + (lane & 3) * 2) =
            __floats2half2_rn(o[j][0] * inv1, o[j][1] * inv1);
        *(__half2*)(Ost + rl2 * 40 + j * 8 + (lane & 3) * 2) =
            __floats2half2_rn(o[j][2] * inv2, o[j][3] * inv2);
    }
    __syncthreads();
    {
        int rowl = tid >> 1, seg = tid & 1;
        uint4* dst = (uint4*)(ao + ((size_t)(b * NQ + hf * 128 + rowl)) * DIMX + h * DH + seg * 16);
        dst[0] = *(uint4*)(Ost + rowl * 40 + seg * 16);
        dst[1] = *(uint4*)(Ost + rowl * 40 + seg * 16 + 8);
    }
}

// ---------------- launch ----------------------------------------------------
extern "C" void kernel_launch(void* const* d_in, const int* in_sizes, int n_in,
                              void* d_out, int out_size) {
    const float* q_w = (const float*)d_in[0];
    const float* kv_w = (const float*)d_in[1];
    const float* q_W = (const float*)d_in[2];
    const float* q_b = (const float*)d_in[3];
    const float* kv_W = (const float*)d_in[4];
    const float* kv_b = (const float*)d_in[5];
    const float* proj_W = (const float*)d_in[6];
    const float* proj_b = (const float*)d_in[7];
    const float* bias_table = (const float*)d_in[8];
    const int* rel_index = (const int*)d_in[9];
    float* out = (float*)d_out;

    __half *qwh, *kvwh, *wqh, *wkvh, *wph, *qph, *kvph, *biash, *aoh;
    cudaGetSymbolAddress((void**)&qwh, g_qwh);
    cudaGetSymbolAddress((void**)&kvwh, g_kvwh);
    cudaGetSymbolAddress((void**)&wqh, g_wqh);
    cudaGetSymbolAddress((void**)&wkvh, g_wkvh);
    cudaGetSymbolAddress((void**)&wph, g_wph);
    cudaGetSymbolAddress((void**)&qph, g_qph);
    cudaGetSymbolAddress((void**)&kvph, g_kvph);
    cudaGetSymbolAddress((void**)&biash, g_biash);
    cudaGetSymbolAddress((void**)&aoh, g_aoh);

    const int GEMM_SMEM = (3 * A_STG + 3 * B_STG) * 2;           // 107520 B
    const int ATTN_SMEM = (2 * 2560 + 2 * 2560 + 128 * 40) * 2;  // 30720 B

    cudaFuncSetAttribute(gemm_qkv, cudaFuncAttributeMaxDynamicSharedMemorySize, GEMM_SMEM);
    cudaFuncSetAttribute(gemm_proj, cudaFuncAttributeMaxDynamicSharedMemorySize, GEMM_SMEM);
    cudaFuncSetAttribute(attn_kernel, cudaFuncAttributeMaxDynamicSharedMemorySize, ATTN_SMEM);

    f2h<<<(4194304 + 255) / 256, 256>>>((const float4*)q_w, qwh, 4194304);
    f2h<<<(9437184 + 255) / 256, 256>>>((const float4*)kv_w, kvwh, 9437184);
    f2h<<<(16384 + 255) / 256, 256>>>((const float4*)q_W, wqh, 16384);
    f2h<<<(32768 + 255) / 256, 256>>>((const float4*)kv_W, wkvh, 32768);
    f2h<<<(16384 + 255) / 256, 256>>>((const float4*)proj_W, wph, 16384);
    bias_gather<<<(NQ * NK + 255) / 256, 256>>>(bias_table, rel_index, biash);

    gemm_qkv<<<5632, 256, GEMM_SMEM>>>(qwh, kvwh, wqh, wkvh, q_b, kv_b, qph, kvph);
    attn_kernel<<<BATCH * HEADS * 2, 256, ATTN_SMEM>>>(qph, kvph, biash, aoh);
    gemm_proj<<<dim3(2, 512), 256, GEMM_SMEM>>>(aoh, wph, proj_b, out);
}